// round 8
// baseline (speedup 1.0000x reference)
#include <cuda_runtime.h>
#include <cuda_bf16.h>
#include <cstdint>
#include <math.h>

#define BB 8
#define LL 4096
#define DD 1024
#define HH 64
#define HDIM 16
#define MROWS (BB*LL)        // 32768
#define KSP2 2048            // [hi | lo] * 1024 elems
#define ROWB 4096            // bytes per [hi|lo] row
#define NSTEP 32             // 1024/32 k-steps (SW64: 32 elems = 64B per step)

#define CHUNK 64
#define NCH (LL/CHUNK)       // 64 time-chunks
#define NCHAINS (BB*HH)      // 512
#define NSUM (NCH*NCHAINS)   // 32768

#define TILEB 8192           // SW64 tile: 128 rows x 64B
#define STAGE (8*TILEB)      // 64KB: A0h,A0l,A1h,A1l,B0h,B0l,B1h,B1l
#define SMEM_SZ (2*STAGE + 1024)

#if defined(__CUDA_ARCH__) && (__CUDA_ARCH__ == 1030) && defined(__CUDA_ARCH_FEAT_SM103_ALL)
#define HAS_TCGEN05 1
#else
#define HAS_TCGEN05 0
#endif

// ---------------- device scratch ------------------------------------------
__device__ __nv_bfloat16 g_a2[(size_t)MROWS * KSP2];   // split xn [hi|lo]
__device__ __nv_bfloat16 g_h2[(size_t)MROWS * KSP2];   // split hs [hi|lo]
__device__ float g_q [(size_t)MROWS * DD];
__device__ float g_k [(size_t)MROWS * DD];
__device__ float g_v [(size_t)MROWS * DD];
__device__ float g_if[(size_t)MROWS * 2 * HH];
__device__ __nv_bfloat16 g_qw2[(size_t)DD * KSP2];
__device__ __nv_bfloat16 g_kw2[(size_t)DD * KSP2];
__device__ __nv_bfloat16 g_vw2[(size_t)DD * KSP2];
__device__ __nv_bfloat16 g_ow2[(size_t)DD * KSP2];
__device__ __nv_bfloat16 g_wif2[(size_t)(2*HH) * KSP2];
__device__ float g_wif[2 * HH * DD];
__device__ float g_bif[2 * HH];
// chunked-scan summaries / entering states
__device__ float g_Cloc[(size_t)NSUM * 256];
__device__ float g_nloc[(size_t)NSUM * 16];
__device__ float g_mloc[NSUM];
__device__ float g_Floc[NSUM];
__device__ float g_Cin [(size_t)NSUM * 256];
__device__ float g_nin [(size_t)NSUM * 16];
__device__ float g_min [NSUM];

// ---------------- PTX helpers (sm_103a only) -------------------------------
__device__ __forceinline__ uint32_t smem_u32(const void* p) {
    uint32_t a;
    asm("{ .reg .u64 t; cvta.to.shared.u64 t, %1; cvt.u32.u64 %0, t; }"
        : "=r"(a) : "l"(p));
    return a;
}

#if HAS_TCGEN05
__device__ __forceinline__ uint32_t elect_one_pred() {
    uint32_t pred;
    asm volatile("{\n\t.reg .pred p;\n\telect.sync _|p, 0xFFFFFFFF;\n\t"
                 "selp.b32 %0, 1, 0, p;\n\t}" : "=r"(pred));
    return pred;
}
#define TCGEN05_ALLOC(saddr, n) \
    asm volatile("tcgen05.alloc.cta_group::1.sync.aligned.shared::cta.b32 [%0], %1;" \
                 :: "r"((uint32_t)(saddr)), "r"((uint32_t)(n)) : "memory")
#define TCGEN05_DEALLOC(taddr, n) \
    asm volatile("tcgen05.dealloc.cta_group::1.sync.aligned.b32 %0, %1;" \
                 :: "r"(taddr), "r"((uint32_t)(n)))
#define TCGEN05_RELINQ() \
    asm volatile("tcgen05.relinquish_alloc_permit.cta_group::1.sync.aligned;")
#define TCGEN05_COMMIT(mbar) \
    asm volatile("tcgen05.commit.cta_group::1.mbarrier::arrive::one.shared::cluster.b64 [%0];" \
                 :: "r"((uint32_t)(mbar)) : "memory")
#define TCGEN05_FENCE_AFTER() \
    asm volatile("tcgen05.fence::after_thread_sync;" ::: "memory")
#define TCGEN05_FENCE_BEFORE() \
    asm volatile("tcgen05.fence::before_thread_sync;" ::: "memory")
#define TCGEN05_WAIT_LD() \
    asm volatile("tcgen05.wait::ld.sync.aligned;" ::: "memory")
#define FENCE_PROXY_ASYNC() \
    asm volatile("fence.proxy.async.shared::cta;" ::: "memory")
#define MBARRIER_INIT(mbar, cnt) \
    asm volatile("mbarrier.init.shared.b64 [%0], %1;" \
                 :: "r"((uint32_t)(mbar)), "r"((uint32_t)(cnt)) : "memory")
__device__ __forceinline__ void mbar_inval(uint32_t a) {
    asm volatile("mbarrier.inval.shared.b64 [%0];" :: "r"(a) : "memory");
}
#define MBARRIER_WAIT_PARITY(mbar, par) do { \
    uint32_t _m = (uint32_t)(mbar); uint32_t _p = (uint32_t)(par); uint32_t _d; \
    asm volatile("{\n\t.reg .pred p;\n\t" \
        "mbarrier.try_wait.parity.acquire.cta.shared::cta.b64 p, [%1], %2;\n\t" \
        "selp.b32 %0, 1, 0, p;\n\t}" : "=r"(_d) : "r"(_m), "r"(_p) : "memory"); \
    if (!_d) { \
        asm volatile("{\n\t.reg .pred P1;\n\t" \
            "WL_%=:\n\t" \
            "mbarrier.try_wait.parity.acquire.cta.shared::cta.b64 P1, [%0], %1, 0x989680;\n\t" \
            "@P1 bra.uni WD_%=;\n\tbra.uni WL_%=;\n\tWD_%=:\n\t}" \
            :: "r"(_m), "r"(_p) : "memory"); \
    } \
} while (0)
#define TCGEN05_MMA_F16_SS(dtm, adesc, bdesc, idesc, en) do { \
    uint32_t _e = (en) ? 1u : 0u; \
    asm volatile("{\n\t.reg .pred p;\n\tsetp.ne.u32 p, %5, 0;\n\t" \
        "tcgen05.mma.cta_group::1.kind::f16 [%0], %1, %2, %3, {%4, %4, %4, %4}, p;\n\t}" \
        :: "r"(dtm), "l"(adesc), "l"(bdesc), "r"(idesc), "r"(0u), "r"(_e) : "memory"); \
} while (0)
#define TCGEN05_LD_X32(r, taddr) \
    asm volatile("tcgen05.ld.sync.aligned.32x32b.x32.b32 " \
        "{%0, %1, %2, %3, %4, %5, %6, %7, %8, %9, %10, %11, %12, %13, %14, %15, " \
        "%16, %17, %18, %19, %20, %21, %22, %23, %24, %25, %26, %27, %28, %29, %30, %31}, [%32];" \
        : "=r"((r)[0]),  "=r"((r)[1]),  "=r"((r)[2]),  "=r"((r)[3]), \
          "=r"((r)[4]),  "=r"((r)[5]),  "=r"((r)[6]),  "=r"((r)[7]), \
          "=r"((r)[8]),  "=r"((r)[9]),  "=r"((r)[10]), "=r"((r)[11]), \
          "=r"((r)[12]), "=r"((r)[13]), "=r"((r)[14]), "=r"((r)[15]), \
          "=r"((r)[16]), "=r"((r)[17]), "=r"((r)[18]), "=r"((r)[19]), \
          "=r"((r)[20]), "=r"((r)[21]), "=r"((r)[22]), "=r"((r)[23]), \
          "=r"((r)[24]), "=r"((r)[25]), "=r"((r)[26]), "=r"((r)[27]), \
          "=r"((r)[28]), "=r"((r)[29]), "=r"((r)[30]), "=r"((r)[31]) \
        : "r"(taddr))

// K-major SW64 descriptor: layout=4 (SW64), version=1, SBO=32 (512B = 8 rows x 64B atom), LBO=1
static constexpr uint64_t SMEM_DESC_BASE_SW64 =
    (uint64_t(4)  << 61) | (uint64_t(1) << 46) | (uint64_t(32) << 32) | (uint64_t(1) << 16);
#define MAKE_SMEM_DESC64(a) (SMEM_DESC_BASE_SW64 | ((uint64_t)((a) >> 4) & 0x3FFF))

// idesc: f32 accum, bf16 A/B, M=128, N=128
static constexpr uint32_t MMA_IDESC =
    (1u << 4) | (1u << 7) | (1u << 10) | ((128u / 8) << 17) | ((128u / 16) << 24);
#endif  // HAS_TCGEN05

#define SWZ64(off) ((off) ^ (((off) >> 3) & 0x30))

// ---------------- bf16 split helper ----------------------------------------
__device__ __forceinline__ void split2(float v, __nv_bfloat16& hi, __nv_bfloat16& lo) {
    hi = __float2bfloat16(v);
    lo = __float2bfloat16(v - __bfloat162float(hi));
}

// ---------------- LayerNorm fused with [hi|lo] bf16 output ------------------
__global__ void ln_split_kernel(const float* __restrict__ x,
                                const float* __restrict__ gamma,
                                const float* __restrict__ beta) {
    __shared__ float s_sum[8], s_sq[8];
    const int row = blockIdx.x;
    const float4* xr = reinterpret_cast<const float4*>(x) + (size_t)row * (DD / 4);
    float4 v = xr[threadIdx.x];
    float s = v.x + v.y + v.z + v.w;
    float q = v.x * v.x + v.y * v.y + v.z * v.z + v.w * v.w;
    #pragma unroll
    for (int o = 16; o; o >>= 1) {
        s += __shfl_xor_sync(0xffffffffu, s, o);
        q += __shfl_xor_sync(0xffffffffu, q, o);
    }
    const int warp = threadIdx.x >> 5, lane = threadIdx.x & 31;
    if (lane == 0) { s_sum[warp] = s; s_sq[warp] = q; }
    __syncthreads();
    if (warp == 0) {
        s = (lane < 8) ? s_sum[lane] : 0.f;
        q = (lane < 8) ? s_sq[lane] : 0.f;
        #pragma unroll
        for (int o = 4; o; o >>= 1) {
            s += __shfl_xor_sync(0xffffffffu, s, o);
            q += __shfl_xor_sync(0xffffffffu, q, o);
        }
        if (lane == 0) { s_sum[0] = s; s_sq[0] = q; }
    }
    __syncthreads();
    const float mean = s_sum[0] * (1.f / DD);
    const float var  = s_sq[0] * (1.f / DD) - mean * mean;
    const float rstd = rsqrtf(var + 1e-5f);
    const float4 gg = reinterpret_cast<const float4*>(gamma)[threadIdx.x];
    const float4 bb = reinterpret_cast<const float4*>(beta)[threadIdx.x];
    float o0 = (v.x - mean) * rstd * gg.x + bb.x;
    float o1 = (v.y - mean) * rstd * gg.y + bb.y;
    float o2 = (v.z - mean) * rstd * gg.z + bb.z;
    float o3 = (v.w - mean) * rstd * gg.w + bb.w;
    __nv_bfloat16 h0, h1, h2, h3, l0, l1, l2, l3;
    split2(o0, h0, l0); split2(o1, h1, l1); split2(o2, h2, l2); split2(o3, h3, l3);
    __nv_bfloat16* dst = g_a2 + (size_t)row * KSP2 + threadIdx.x * 4;
    __nv_bfloat162 hA(h0, h1), hB(h2, h3), lA(l0, l1), lB(l2, l3);
    reinterpret_cast<__nv_bfloat162*>(dst)[0] = hA;
    reinterpret_cast<__nv_bfloat162*>(dst)[1] = hB;
    reinterpret_cast<__nv_bfloat162*>(dst + 1024)[0] = lA;
    reinterpret_cast<__nv_bfloat162*>(dst + 1024)[1] = lB;
}

// ---------------- generic fp32 -> [hi|lo] bf16 [rows,2048] ------------------
__global__ void split_kernel(const float* __restrict__ src, __nv_bfloat16* __restrict__ dst,
                             int rows) {
    int i = blockIdx.x * blockDim.x + threadIdx.x;
    if (i >= rows * 256) return;
    int row = i >> 8;
    int g = i & 255;
    float4 v = reinterpret_cast<const float4*>(src + (size_t)row * DD)[g];
    __nv_bfloat16 h0, h1, h2, h3, l0, l1, l2, l3;
    split2(v.x, h0, l0); split2(v.y, h1, l1); split2(v.z, h2, l2); split2(v.w, h3, l3);
    __nv_bfloat16* d = dst + (size_t)row * KSP2 + g * 4;
    __nv_bfloat162 hA(h0, h1), hB(h2, h3), lA(l0, l1), lB(l2, l3);
    reinterpret_cast<__nv_bfloat162*>(d)[0] = hA;
    reinterpret_cast<__nv_bfloat162*>(d)[1] = hB;
    reinterpret_cast<__nv_bfloat162*>(d + 1024)[0] = lA;
    reinterpret_cast<__nv_bfloat162*>(d + 1024)[1] = lB;
}

// ---------------- pack i/f weights -----------------------------------------
__global__ void combine_if_kernel(const float* __restrict__ iw,
                                  const float* __restrict__ ib,
                                  const float* __restrict__ fw,
                                  const float* __restrict__ fb) {
    int idx = blockIdx.x * blockDim.x + threadIdx.x;
    if (idx < 2 * HH * DD) {
        int nrow = idx / DD;
        g_wif[idx] = (nrow < HH) ? iw[idx] : fw[idx - HH * DD];
    }
    if (idx < 2 * HH) g_bif[idx] = (idx < HH) ? ib[idx] : fb[idx - HH];
}

// ---------------- tcgen05 GEMM, BM=256 x BN=(ntn*128), SW64, [hi|lo] --------
// out[m,n] = scale*(Ah·Bh + Ah·Bl + Al·Bh + bias) (+resid)
template <bool RESID>
__global__ void __launch_bounds__(256, 1) mma_gemm_kernel(
    const __nv_bfloat16* __restrict__ A2,
    const __nv_bfloat16* __restrict__ B2,
    const float* __restrict__ bias,
    const float* __restrict__ resid,
    float* __restrict__ out,
    int N, float scale, int ntn)
{
#if HAS_TCGEN05
    extern __shared__ char smem_raw[];
    char* smem = (char*)(((uintptr_t)smem_raw + 1023) & ~(uintptr_t)1023);
    __shared__ __align__(16) uint64_t s_mbar[2];
    __shared__ uint32_t s_tmem;

    const int tid = threadIdx.x;
    const int wid = tid >> 5;
    const int bm = blockIdx.y * 256;           // 2 M-tiles of 128
    const int bn = blockIdx.x * (128 * ntn);   // ntn N-tiles of 128
    const uint32_t smem_base = smem_u32(smem);

    if (wid == 0) {
        TCGEN05_ALLOC(smem_u32(&s_tmem), 512);
        TCGEN05_RELINQ();
    }
    if (tid == 0) {
        MBARRIER_INIT(smem_u32(&s_mbar[0]), 1);
        MBARRIER_INIT(smem_u32(&s_mbar[1]), 1);
    }
    __syncthreads();
    const uint32_t tmem_d = s_tmem;
    const uint32_t mbar0 = smem_u32(&s_mbar[0]);
    const uint32_t mbar1 = smem_u32(&s_mbar[1]);

    const char* Abase = (const char*)(A2 + (size_t)bm * KSP2);
    const char* Bbase = (const char*)(B2 + (size_t)bn * KSP2);

    // one 8KB SW64 tile: 128 rows x 64B
    auto load_tile = [&](const char* src, char* dst) {
        #pragma unroll
        for (int i = 0; i < 2; ++i) {
            int cidx = tid + i * 256;        // 0..511
            int row = cidx >> 2;             // 4 x 16B per row
            int c16 = cidx & 3;
            uint4 v = *(const uint4*)(src + (size_t)row * ROWB + c16 * 16);
            *(uint4*)(dst + SWZ64(row * 64 + c16 * 16)) = v;
        }
    };
    auto load_step = [&](int kc, int s) {
        char* sb = smem + s * STAGE;
        const size_t ko = (size_t)kc * 64;    // byte offset of hi chunk in row
        // A: 2 M-tiles, hi+lo
        #pragma unroll
        for (int i = 0; i < 2; ++i) {
            const char* a = Abase + (size_t)(i * 128) * ROWB;
            load_tile(a + ko,        sb + (i * 2 + 0) * TILEB);
            load_tile(a + 2048 + ko, sb + (i * 2 + 1) * TILEB);
        }
        // B: ntn N-tiles, hi+lo
        for (int j = 0; j < ntn; ++j) {
            const char* b = Bbase + (size_t)(j * 128) * ROWB;
            load_tile(b + ko,        sb + 4 * TILEB + (j * 2 + 0) * TILEB);
            load_tile(b + 2048 + ko, sb + 4 * TILEB + (j * 2 + 1) * TILEB);
        }
    };

    load_step(0, 0);
    __syncthreads();

    int phase0 = 0, phase1 = 0;
    for (int kc = 0; kc < NSTEP; ++kc) {
        const int s = kc & 1;
        if (wid == 0) {
            FENCE_PROXY_ASYNC();
            if (elect_one_pred()) {
                const uint32_t base = smem_base + s * STAGE;
                for (int i = 0; i < 2; ++i) {
                    const uint64_t dAh = MAKE_SMEM_DESC64(base + (i * 2 + 0) * TILEB);
                    const uint64_t dAl = MAKE_SMEM_DESC64(base + (i * 2 + 1) * TILEB);
                    for (int j = 0; j < ntn; ++j) {
                        const uint64_t dBh = MAKE_SMEM_DESC64(base + 4 * TILEB + (j * 2 + 0) * TILEB);
                        const uint64_t dBl = MAKE_SMEM_DESC64(base + 4 * TILEB + (j * 2 + 1) * TILEB);
                        const uint32_t dt = tmem_d + (i * ntn + j) * 128;
                        #pragma unroll
                        for (int g = 0; g < 2; ++g) {   // K=32 per step, 16 per dispatch
                            TCGEN05_MMA_F16_SS(dt, dAh + g * 2, dBh + g * 2, MMA_IDESC,
                                               (kc > 0) || (g > 0));
                            TCGEN05_MMA_F16_SS(dt, dAh + g * 2, dBl + g * 2, MMA_IDESC, true);
                            TCGEN05_MMA_F16_SS(dt, dAl + g * 2, dBh + g * 2, MMA_IDESC, true);
                        }
                    }
                }
                TCGEN05_COMMIT(s == 0 ? mbar0 : mbar1);
            }
        }
        if (kc + 1 < NSTEP) {
            const int s2 = (kc + 1) & 1;
            if (kc >= 1) {
                if (s2 == 0) { MBARRIER_WAIT_PARITY(mbar0, phase0); phase0 ^= 1; }
                else         { MBARRIER_WAIT_PARITY(mbar1, phase1); phase1 ^= 1; }
            }
            load_step(kc + 1, s2);
        }
        __syncthreads();
    }
    // last step (kc=31, odd) committed to mbar1
    MBARRIER_WAIT_PARITY(mbar1, phase1);
    TCGEN05_FENCE_AFTER();

    // epilogue: per D tile (i,j); warps 0-3 cols 0..63, warps 4-7 cols 64..127
    const int colbase = (wid >> 2) * 64;
    for (int i = 0; i < 2; ++i) {
        const int row = bm + i * 128 + (wid & 3) * 32 + (tid & 31);
        for (int j = 0; j < ntn; ++j) {
            #pragma unroll
            for (int cb = 0; cb < 64; cb += 32) {
                uint32_t dr[32];
                TCGEN05_LD_X32(dr, tmem_d + (i * ntn + j) * 128 + colbase + cb);
                TCGEN05_WAIT_LD();
                TCGEN05_FENCE_BEFORE();
                #pragma unroll
                for (int c = 0; c < 32; c += 4) {
                    const int col = bn + j * 128 + colbase + cb + c;
                    float4 bs = *(const float4*)(bias + col);
                    float4 o;
                    o.x = scale * (__uint_as_float(dr[c + 0]) + bs.x);
                    o.y = scale * (__uint_as_float(dr[c + 1]) + bs.y);
                    o.z = scale * (__uint_as_float(dr[c + 2]) + bs.z);
                    o.w = scale * (__uint_as_float(dr[c + 3]) + bs.w);
                    if (RESID) {
                        float4 r = *(const float4*)(resid + (size_t)row * N + col);
                        o.x += r.x; o.y += r.y; o.z += r.z; o.w += r.w;
                    }
                    *(float4*)(out + (size_t)row * N + col) = o;
                }
            }
        }
    }
    __syncthreads();
    if (tid == 0) { mbar_inval(mbar0); mbar_inval(mbar1); }
    __syncthreads();
    if (wid == 0) TCGEN05_DEALLOC(tmem_d, 512);
#else
    // Fallback for the compute_103 PTX pass (never run on sm_103a HW).
    const int tid = threadIdx.x;
    const int bm = blockIdx.y * 256;
    const int bn = blockIdx.x * (128 * ntn);
    const int r0 = (tid >> 4) * 16;
    const int c0 = (tid & 15) * 8;
    for (int t = 0; t < ntn; ++t)
    for (int i = 0; i < 16; ++i) {
        const int row = bm + r0 + i;
        const __nv_bfloat16* ar = A2 + (size_t)row * KSP2;
        for (int j = 0; j < 8; ++j) {
            const int col = bn + t * 128 + c0 + j;
            const __nv_bfloat16* br = B2 + (size_t)col * KSP2;
            float acc = 0.f;
            for (int k = 0; k < 1024; ++k) {
                float ah = __bfloat162float(ar[k]), al = __bfloat162float(ar[1024 + k]);
                float bh = __bfloat162float(br[k]), bl = __bfloat162float(br[1024 + k]);
                acc += ah * bh + ah * bl + al * bh;
            }
            float o = scale * (acc + bias[col]);
            if (RESID) o += resid[(size_t)row * N + col];
            out[(size_t)row * N + col] = o;
        }
    }
#endif
}

// ---------------- chunked scan, phase 1: per-chunk local scan ---------------
__global__ void __launch_bounds__(256) scan_phase1_kernel() {
    const int tid = threadIdx.x;
    const int gid = blockIdx.x * 16 + (tid >> 4);   // 0..NSUM-1
    const int e = tid & 15;
    const int j = gid >> 9;          // chunk
    const int c = gid & 511;         // chain
    const int b = c >> 6, h = c & 63;
    const int t0 = j * CHUNK;

    size_t off = ((size_t)b * LL + t0) * DD + h * HDIM + e;
    size_t offIF = ((size_t)b * LL + t0) * (2 * HH);

    float C[16];
    #pragma unroll
    for (int d = 0; d < 16; ++d) C[d] = 0.f;
    float n = 0.f, m = -1e30f, F = 0.f;

    for (int t = 0; t < CHUNK; ++t) {
        const float ke = g_k[off], ve = g_v[off];
        const float it = g_if[offIF + h];
        const float ft = g_if[offIF + HH + h];
        const float m_new = fmaxf(ft + m, it);
        const float fd = __expf(ft + m - m_new);
        const float id = __expf(it - m_new);
        m = m_new; F += ft;
        const float kid = id * ke;
        n = fd * n + kid;
        #pragma unroll
        for (int d = 0; d < 16; ++d) {
            const float vd = __shfl_sync(0xffffffffu, ve, d, 16);
            C[d] = fd * C[d] + vd * kid;
        }
        off += DD; offIF += 2 * HH;
    }
    float* cs = g_Cloc + (size_t)gid * 256;
    #pragma unroll
    for (int d = 0; d < 16; ++d) cs[d * 16 + e] = C[d];
    g_nloc[(size_t)gid * 16 + e] = n;
    if (e == 0) { g_mloc[gid] = m; g_Floc[gid] = F; }
}

// ---------------- phase 2: serial combine across chunks (per chain) ---------
__global__ void __launch_bounds__(256) scan_phase2_kernel() {
    const int tid = threadIdx.x;
    const int c = blockIdx.x * 16 + (tid >> 4);     // chain 0..511
    const int e = tid & 15;

    float C[16];
    #pragma unroll
    for (int d = 0; d < 16; ++d) C[d] = 0.f;
    float n = 0.f, m = 0.f;                          // reference init: zeros

    for (int j = 0; j < NCH; ++j) {
        const int sid = j * NCHAINS + c;
        float* ci = g_Cin + (size_t)sid * 256;
        #pragma unroll
        for (int d = 0; d < 16; ++d) ci[d * 16 + e] = C[d];
        g_nin[(size_t)sid * 16 + e] = n;
        if (e == 0) g_min[sid] = m;
        const float ml = g_mloc[sid];
        const float F  = g_Floc[sid];
        const float mo = fmaxf(m + F, ml);
        const float a  = __expf(m + F - mo);
        const float bb = __expf(ml - mo);
        const float* cl = g_Cloc + (size_t)sid * 256;
        #pragma unroll
        for (int d = 0; d < 16; ++d) C[d] = a * C[d] + bb * cl[d * 16 + e];
        n = a * n + bb * g_nloc[(size_t)sid * 16 + e];
        m = mo;
    }
}

// ---------------- phase 3: replay chunk from entering state, emit h ---------
__global__ void __launch_bounds__(256) scan_phase3_kernel() {
    const int tid = threadIdx.x;
    const int gid = blockIdx.x * 16 + (tid >> 4);
    const int e = tid & 15;
    const int j = gid >> 9;
    const int c = gid & 511;
    const int b = c >> 6, h = c & 63;
    const int t0 = j * CHUNK;

    size_t off = ((size_t)b * LL + t0) * DD + h * HDIM + e;
    size_t offIF = ((size_t)b * LL + t0) * (2 * HH);
    size_t h2off = ((size_t)b * LL + t0) * KSP2 + h * HDIM + e;

    const float* ci = g_Cin + (size_t)gid * 256;
    float C[16];
    #pragma unroll
    for (int d = 0; d < 16; ++d) C[d] = ci[d * 16 + e];
    float n = g_nin[(size_t)gid * 16 + e];
    float m = g_min[gid];

    for (int t = 0; t < CHUNK; ++t) {
        const float qe = g_q[off], ke = g_k[off], ve = g_v[off];
        const float it = g_if[offIF + h];
        const float ft = g_if[offIF + HH + h];
        const float m_new = fmaxf(ft + m, it);
        const float fd = __expf(ft + m - m_new);
        const float id = __expf(it - m_new);
        m = m_new;
        const float kid = id * ke;
        n = fd * n + kid;

        float cq = 0.f;
        #pragma unroll
        for (int d = 0; d < 16; ++d) {
            const float vd = __shfl_sync(0xffffffffu, ve, d, 16);
            const float qd = __shfl_sync(0xffffffffu, qe, d, 16);
            C[d] = fd * C[d] + vd * kid;
            cq = fmaf(C[d], qd, cq);
        }

        float nq = n * qe;
        #pragma unroll
        for (int o = 8; o; o >>= 1) nq += __shfl_xor_sync(0xffffffffu, nq, o, 16);
        const float denom = fmaxf(fabsf(nq), 1.0f);

        const float hval = cq / denom;
        __nv_bfloat16 hh, hl;
        split2(hval, hh, hl);
        g_h2[h2off] = hh;
        g_h2[h2off + 1024] = hl;

        off += DD; offIF += 2 * HH; h2off += KSP2;
    }
}

// ---------------- launch ----------------------------------------------------
extern "C" void kernel_launch(void* const* d_in, const int* in_sizes, int n_in,
                              void* d_out, int out_size) {
    (void)in_sizes; (void)n_in; (void)out_size;
    const float* x     = (const float*)d_in[0];
    const float* gamma = (const float*)d_in[1];
    const float* beta  = (const float*)d_in[2];
    const float* qw    = (const float*)d_in[3];
    const float* qb    = (const float*)d_in[4];
    const float* kw    = (const float*)d_in[5];
    const float* kb    = (const float*)d_in[6];
    const float* vw    = (const float*)d_in[7];
    const float* vb    = (const float*)d_in[8];
    const float* ow    = (const float*)d_in[9];
    const float* ob    = (const float*)d_in[10];
    const float* iw    = (const float*)d_in[11];
    const float* ib    = (const float*)d_in[12];
    const float* fw    = (const float*)d_in[13];
    const float* fb    = (const float*)d_in[14];
    float* out = (float*)d_out;

    __nv_bfloat16 *a2, *h2, *qw2, *kw2, *vw2, *ow2, *wif2;
    float *qp, *kp, *vp, *ifp, *wif, *bif;
    cudaGetSymbolAddress((void**)&a2,   g_a2);
    cudaGetSymbolAddress((void**)&h2,   g_h2);
    cudaGetSymbolAddress((void**)&qw2,  g_qw2);
    cudaGetSymbolAddress((void**)&kw2,  g_kw2);
    cudaGetSymbolAddress((void**)&vw2,  g_vw2);
    cudaGetSymbolAddress((void**)&ow2,  g_ow2);
    cudaGetSymbolAddress((void**)&wif2, g_wif2);
    cudaGetSymbolAddress((void**)&qp,   g_q);
    cudaGetSymbolAddress((void**)&kp,   g_k);
    cudaGetSymbolAddress((void**)&vp,   g_v);
    cudaGetSymbolAddress((void**)&ifp,  g_if);
    cudaGetSymbolAddress((void**)&wif,  g_wif);
    cudaGetSymbolAddress((void**)&bif,  g_bif);

    cudaFuncSetAttribute(mma_gemm_kernel<false>,
                         cudaFuncAttributeMaxDynamicSharedMemorySize, SMEM_SZ);
    cudaFuncSetAttribute(mma_gemm_kernel<true>,
                         cudaFuncAttributeMaxDynamicSharedMemorySize, SMEM_SZ);

    // 1. LN + split
    ln_split_kernel<<<MROWS, 256>>>(x, gamma, beta);
    // 2. weight prep
    combine_if_kernel<<<(2 * HH * DD + 255) / 256, 256>>>(iw, ib, fw, fb);
    split_kernel<<<(DD * 256 + 255) / 256, 256>>>(qw, qw2, DD);
    split_kernel<<<(DD * 256 + 255) / 256, 256>>>(kw, kw2, DD);
    split_kernel<<<(DD * 256 + 255) / 256, 256>>>(vw, vw2, DD);
    split_kernel<<<(DD * 256 + 255) / 256, 256>>>(ow, ow2, DD);
    split_kernel<<<(2 * HH * 256 + 255) / 256, 256>>>(wif, wif2, 2 * HH);

    // 3. projections on tcgen05 (BM=256, BN=256)
    dim3 gridBig(DD / 256, MROWS / 256);   // (4, 128)
    dim3 gridIF(1, MROWS / 256);           // (1, 128), 1 N-tile
    mma_gemm_kernel<false><<<gridBig, 256, SMEM_SZ>>>(a2, qw2, qb, nullptr, qp, DD, 1.0f, 2);
    mma_gemm_kernel<false><<<gridBig, 256, SMEM_SZ>>>(a2, kw2, kb, nullptr, kp, DD, 0.25f, 2);
    mma_gemm_kernel<false><<<gridBig, 256, SMEM_SZ>>>(a2, vw2, vb, nullptr, vp, DD, 1.0f, 2);
    mma_gemm_kernel<false><<<gridIF, 256, SMEM_SZ>>>(a2, wif2, bif, nullptr, ifp, 2 * HH, 1.0f, 1);

    // 4. chunked parallel scan
    scan_phase1_kernel<<<NSUM / 16, 256>>>();
    scan_phase2_kernel<<<NCHAINS / 16, 256>>>();
    scan_phase3_kernel<<<NSUM / 16, 256>>>();

    // 5. output projection + residual
    mma_gemm_kernel<true><<<gridBig, 256, SMEM_SZ>>>(h2, ow2, ob, x, out, DD, 1.0f, 2);
}

// round 10
// speedup vs baseline: 1.5415x; 1.5415x over previous
#include <cuda_runtime.h>
#include <cuda_bf16.h>
#include <cstdint>
#include <math.h>

#define BB 8
#define LL 4096
#define DD 1024
#define HH 64
#define HDIM 16
#define MROWS (BB*LL)        // 32768
#define KSP2 2048            // [hi | lo] * 1024
#define ROWB 4096            // bytes per [hi|lo] row
#define NSTEP 16             // 1024/64 k-steps in GEMM

#define CHUNK 64
#define NCH (LL/CHUNK)       // 64 time-chunks
#define NCHAINS (BB*HH)      // 512
#define NSUM (NCH*NCHAINS)   // 32768

#define STAGE 98304          // 96KB: Ah,Al,B0h,B0l,B1h,B1l (16KB each)
#define SMEM_SZ (2*STAGE + 1024)

#if defined(__CUDA_ARCH__) && (__CUDA_ARCH__ == 1030) && defined(__CUDA_ARCH_FEAT_SM103_ALL)
#define HAS_TCGEN05 1
#else
#define HAS_TCGEN05 0
#endif

// ---------------- device scratch ------------------------------------------
__device__ __nv_bfloat16 g_a2[(size_t)MROWS * KSP2];   // split xn [hi|lo]
__device__ __nv_bfloat16 g_h2[(size_t)MROWS * KSP2];   // split hs [hi|lo]
__device__ float g_q [(size_t)MROWS * DD];
__device__ float g_k [(size_t)MROWS * DD];
__device__ float g_v [(size_t)MROWS * DD];
__device__ float g_if[(size_t)MROWS * 2 * HH];
__device__ __nv_bfloat16 g_qw2[(size_t)DD * KSP2];
__device__ __nv_bfloat16 g_kw2[(size_t)DD * KSP2];
__device__ __nv_bfloat16 g_vw2[(size_t)DD * KSP2];
__device__ __nv_bfloat16 g_ow2[(size_t)DD * KSP2];
__device__ __nv_bfloat16 g_wif2[(size_t)(2*HH) * KSP2];
__device__ float g_wif[2 * HH * DD];
__device__ float g_bif[2 * HH];
// chunked-scan summaries / entering states
__device__ float g_Cloc[(size_t)NSUM * 256];
__device__ float g_nloc[(size_t)NSUM * 16];
__device__ float g_mloc[NSUM];
__device__ float g_Floc[NSUM];
__device__ float g_Cin [(size_t)NSUM * 256];
__device__ float g_nin [(size_t)NSUM * 16];
__device__ float g_min [NSUM];

// ---------------- PTX helpers ------------------------------------------------
__device__ __forceinline__ uint32_t smem_u32(const void* p) {
    uint32_t a;
    asm("{ .reg .u64 t; cvta.to.shared.u64 t, %1; cvt.u32.u64 %0, t; }"
        : "=r"(a) : "l"(p));
    return a;
}
__device__ __forceinline__ void cp_async16(uint32_t saddr, const void* g) {
    asm volatile("cp.async.cg.shared.global [%0], [%1], 16;"
                 :: "r"(saddr), "l"(g) : "memory");
}
#define CP_COMMIT() asm volatile("cp.async.commit_group;" ::: "memory")
#define CP_WAIT0()  asm volatile("cp.async.wait_group 0;" ::: "memory")

#if HAS_TCGEN05
__device__ __forceinline__ uint32_t elect_one_pred() {
    uint32_t pred;
    asm volatile("{\n\t.reg .pred p;\n\telect.sync _|p, 0xFFFFFFFF;\n\t"
                 "selp.b32 %0, 1, 0, p;\n\t}" : "=r"(pred));
    return pred;
}
#define TCGEN05_ALLOC(saddr, n) \
    asm volatile("tcgen05.alloc.cta_group::1.sync.aligned.shared::cta.b32 [%0], %1;" \
                 :: "r"((uint32_t)(saddr)), "r"((uint32_t)(n)) : "memory")
#define TCGEN05_DEALLOC(taddr, n) \
    asm volatile("tcgen05.dealloc.cta_group::1.sync.aligned.b32 %0, %1;" \
                 :: "r"(taddr), "r"((uint32_t)(n)))
#define TCGEN05_RELINQ() \
    asm volatile("tcgen05.relinquish_alloc_permit.cta_group::1.sync.aligned;")
#define TCGEN05_COMMIT(mbar) \
    asm volatile("tcgen05.commit.cta_group::1.mbarrier::arrive::one.shared::cluster.b64 [%0];" \
                 :: "r"((uint32_t)(mbar)) : "memory")
#define TCGEN05_FENCE_AFTER() \
    asm volatile("tcgen05.fence::after_thread_sync;" ::: "memory")
#define TCGEN05_FENCE_BEFORE() \
    asm volatile("tcgen05.fence::before_thread_sync;" ::: "memory")
#define TCGEN05_WAIT_LD() \
    asm volatile("tcgen05.wait::ld.sync.aligned;" ::: "memory")
#define FENCE_PROXY_ASYNC() \
    asm volatile("fence.proxy.async.shared::cta;" ::: "memory")
#define MBARRIER_INIT(mbar, cnt) \
    asm volatile("mbarrier.init.shared.b64 [%0], %1;" \
                 :: "r"((uint32_t)(mbar)), "r"((uint32_t)(cnt)) : "memory")
__device__ __forceinline__ void mbar_inval(uint32_t a) {
    asm volatile("mbarrier.inval.shared.b64 [%0];" :: "r"(a) : "memory");
}
#define MBARRIER_WAIT_PARITY(mbar, par) do { \
    uint32_t _m = (uint32_t)(mbar); uint32_t _p = (uint32_t)(par); uint32_t _d; \
    asm volatile("{\n\t.reg .pred p;\n\t" \
        "mbarrier.try_wait.parity.acquire.cta.shared::cta.b64 p, [%1], %2;\n\t" \
        "selp.b32 %0, 1, 0, p;\n\t}" : "=r"(_d) : "r"(_m), "r"(_p) : "memory"); \
    if (!_d) { \
        asm volatile("{\n\t.reg .pred P1;\n\t" \
            "WL_%=:\n\t" \
            "mbarrier.try_wait.parity.acquire.cta.shared::cta.b64 P1, [%0], %1, 0x989680;\n\t" \
            "@P1 bra.uni WD_%=;\n\tbra.uni WL_%=;\n\tWD_%=:\n\t}" \
            :: "r"(_m), "r"(_p) : "memory"); \
    } \
} while (0)
#define TCGEN05_MMA_F16_SS(dtm, adesc, bdesc, idesc, en) do { \
    uint32_t _e = (en) ? 1u : 0u; \
    asm volatile("{\n\t.reg .pred p;\n\tsetp.ne.u32 p, %5, 0;\n\t" \
        "tcgen05.mma.cta_group::1.kind::f16 [%0], %1, %2, %3, {%4, %4, %4, %4}, p;\n\t}" \
        :: "r"(dtm), "l"(adesc), "l"(bdesc), "r"(idesc), "r"(0u), "r"(_e) : "memory"); \
} while (0)
#define TCGEN05_LD_X32(r, taddr) \
    asm volatile("tcgen05.ld.sync.aligned.32x32b.x32.b32 " \
        "{%0, %1, %2, %3, %4, %5, %6, %7, %8, %9, %10, %11, %12, %13, %14, %15, " \
        "%16, %17, %18, %19, %20, %21, %22, %23, %24, %25, %26, %27, %28, %29, %30, %31}, [%32];" \
        : "=r"((r)[0]),  "=r"((r)[1]),  "=r"((r)[2]),  "=r"((r)[3]), \
          "=r"((r)[4]),  "=r"((r)[5]),  "=r"((r)[6]),  "=r"((r)[7]), \
          "=r"((r)[8]),  "=r"((r)[9]),  "=r"((r)[10]), "=r"((r)[11]), \
          "=r"((r)[12]), "=r"((r)[13]), "=r"((r)[14]), "=r"((r)[15]), \
          "=r"((r)[16]), "=r"((r)[17]), "=r"((r)[18]), "=r"((r)[19]), \
          "=r"((r)[20]), "=r"((r)[21]), "=r"((r)[22]), "=r"((r)[23]), \
          "=r"((r)[24]), "=r"((r)[25]), "=r"((r)[26]), "=r"((r)[27]), \
          "=r"((r)[28]), "=r"((r)[29]), "=r"((r)[30]), "=r"((r)[31]) \
        : "r"(taddr))

static constexpr uint64_t SMEM_DESC_BASE_SW128 =
    (uint64_t(2)  << 61) | (uint64_t(1) << 46) | (uint64_t(64) << 32) | (uint64_t(1) << 16);
#define MAKE_SMEM_DESC(a) (SMEM_DESC_BASE_SW128 | ((uint64_t)((a) >> 4) & 0x3FFF))

// idesc: f32 accum, bf16 A/B, M=128, N=128
static constexpr uint32_t MMA_IDESC =
    (1u << 4) | (1u << 7) | (1u << 10) | ((128u / 8) << 17) | ((128u / 16) << 24);
#endif  // HAS_TCGEN05

#define SWZ128(off) ((off) ^ (((off) >> 3) & 0x70))

// ---------------- bf16 split helper ----------------------------------------
__device__ __forceinline__ void split2(float v, __nv_bfloat16& hi, __nv_bfloat16& lo) {
    hi = __float2bfloat16(v);
    lo = __float2bfloat16(v - __bfloat162float(hi));
}

// ---------------- LayerNorm fused with [hi|lo] bf16 output ------------------
__global__ void ln_split_kernel(const float* __restrict__ x,
                                const float* __restrict__ gamma,
                                const float* __restrict__ beta) {
    __shared__ float s_sum[8], s_sq[8];
    const int row = blockIdx.x;
    const float4* xr = reinterpret_cast<const float4*>(x) + (size_t)row * (DD / 4);
    float4 v = xr[threadIdx.x];
    float s = v.x + v.y + v.z + v.w;
    float q = v.x * v.x + v.y * v.y + v.z * v.z + v.w * v.w;
    #pragma unroll
    for (int o = 16; o; o >>= 1) {
        s += __shfl_xor_sync(0xffffffffu, s, o);
        q += __shfl_xor_sync(0xffffffffu, q, o);
    }
    const int warp = threadIdx.x >> 5, lane = threadIdx.x & 31;
    if (lane == 0) { s_sum[warp] = s; s_sq[warp] = q; }
    __syncthreads();
    if (warp == 0) {
        s = (lane < 8) ? s_sum[lane] : 0.f;
        q = (lane < 8) ? s_sq[lane] : 0.f;
        #pragma unroll
        for (int o = 4; o; o >>= 1) {
            s += __shfl_xor_sync(0xffffffffu, s, o);
            q += __shfl_xor_sync(0xffffffffu, q, o);
        }
        if (lane == 0) { s_sum[0] = s; s_sq[0] = q; }
    }
    __syncthreads();
    const float mean = s_sum[0] * (1.f / DD);
    const float var  = s_sq[0] * (1.f / DD) - mean * mean;
    const float rstd = rsqrtf(var + 1e-5f);
    const float4 gg = reinterpret_cast<const float4*>(gamma)[threadIdx.x];
    const float4 bb = reinterpret_cast<const float4*>(beta)[threadIdx.x];
    float o0 = (v.x - mean) * rstd * gg.x + bb.x;
    float o1 = (v.y - mean) * rstd * gg.y + bb.y;
    float o2 = (v.z - mean) * rstd * gg.z + bb.z;
    float o3 = (v.w - mean) * rstd * gg.w + bb.w;
    __nv_bfloat16 h0, h1, h2, h3, l0, l1, l2, l3;
    split2(o0, h0, l0); split2(o1, h1, l1); split2(o2, h2, l2); split2(o3, h3, l3);
    __nv_bfloat16* dst = g_a2 + (size_t)row * KSP2 + threadIdx.x * 4;
    __nv_bfloat162 hA(h0, h1), hB(h2, h3), lA(l0, l1), lB(l2, l3);
    reinterpret_cast<__nv_bfloat162*>(dst)[0] = hA;
    reinterpret_cast<__nv_bfloat162*>(dst)[1] = hB;
    reinterpret_cast<__nv_bfloat162*>(dst + 1024)[0] = lA;
    reinterpret_cast<__nv_bfloat162*>(dst + 1024)[1] = lB;
}

// ---------------- generic fp32 -> [hi|lo] bf16 [rows,2048] ------------------
__global__ void split_kernel(const float* __restrict__ src, __nv_bfloat16* __restrict__ dst,
                             int rows) {
    int i = blockIdx.x * blockDim.x + threadIdx.x;
    if (i >= rows * 256) return;
    int row = i >> 8;
    int g = i & 255;
    float4 v = reinterpret_cast<const float4*>(src + (size_t)row * DD)[g];
    __nv_bfloat16 h0, h1, h2, h3, l0, l1, l2, l3;
    split2(v.x, h0, l0); split2(v.y, h1, l1); split2(v.z, h2, l2); split2(v.w, h3, l3);
    __nv_bfloat16* d = dst + (size_t)row * KSP2 + g * 4;
    __nv_bfloat162 hA(h0, h1), hB(h2, h3), lA(l0, l1), lB(l2, l3);
    reinterpret_cast<__nv_bfloat162*>(d)[0] = hA;
    reinterpret_cast<__nv_bfloat162*>(d)[1] = hB;
    reinterpret_cast<__nv_bfloat162*>(d + 1024)[0] = lA;
    reinterpret_cast<__nv_bfloat162*>(d + 1024)[1] = lB;
}

// ---------------- pack i/f weights -----------------------------------------
__global__ void combine_if_kernel(const float* __restrict__ iw,
                                  const float* __restrict__ ib,
                                  const float* __restrict__ fw,
                                  const float* __restrict__ fb) {
    int idx = blockIdx.x * blockDim.x + threadIdx.x;
    if (idx < 2 * HH * DD) {
        int nrow = idx / DD;
        g_wif[idx] = (nrow < HH) ? iw[idx] : fw[idx - HH * DD];
    }
    if (idx < 2 * HH) g_bif[idx] = (idx < HH) ? ib[idx] : fb[idx - HH];
}

// ---------------- tcgen05 GEMM (round-7 geometry + cp.async loads) ----------
// out[m,n] = scale*(Ah·Bh + Ah·Bl + Al·Bh + bias) (+resid)
// A2: [M, 2048] bf16 (hi|lo), B2: [N, 2048] bf16 (hi|lo)
template <bool RESID>
__global__ void __launch_bounds__(256, 1) mma_gemm_kernel(
    const __nv_bfloat16* __restrict__ A2,
    const __nv_bfloat16* __restrict__ B2,
    const float* __restrict__ bias,
    const float* __restrict__ resid,
    float* __restrict__ out,
    int N, float scale, int ntiles)
{
#if HAS_TCGEN05
    extern __shared__ char smem_raw[];
    char* smem = (char*)(((uintptr_t)smem_raw + 1023) & ~(uintptr_t)1023);
    __shared__ __align__(16) uint64_t s_mbar[2];
    __shared__ uint32_t s_tmem;

    const int tid = threadIdx.x;
    const int wid = tid >> 5;
    const int bm = blockIdx.y * 128;
    const int bn = blockIdx.x * 256;      // 2 tiles of 128 (ntiles==2)
    const uint32_t smem_base = smem_u32(smem);

    if (wid == 0) {
        TCGEN05_ALLOC(smem_u32(&s_tmem), 256);
        TCGEN05_RELINQ();
    }
    if (tid == 0) {
        MBARRIER_INIT(smem_u32(&s_mbar[0]), 1);
        MBARRIER_INIT(smem_u32(&s_mbar[1]), 1);
    }
    __syncthreads();
    const uint32_t tmem_d = s_tmem;
    const uint32_t mbar0 = smem_u32(&s_mbar[0]);
    const uint32_t mbar1 = smem_u32(&s_mbar[1]);

    const char* Abase  = (const char*)(A2 + (size_t)bm * KSP2);
    const char* B0base = (const char*)(B2 + (size_t)bn * KSP2);
    const char* B1base = B0base + (size_t)128 * ROWB;

    // one 16KB SW128 tile via cp.async: 128 rows x 128B
    const int t_row = tid >> 1;            // 0..127 (2 threads per row)
    const int t_c32 = (tid & 1) * 32;      // 0 or 32 (2 x 16B each)
    auto load_tile = [&](const char* src, uint32_t dsm) {
        const char* g = src + (size_t)t_row * ROWB + t_c32;
        uint32_t s0 = dsm + SWZ128((uint32_t)(t_row * 128 + t_c32));
        uint32_t s1 = dsm + SWZ128((uint32_t)(t_row * 128 + t_c32 + 16));
        uint32_t s2 = dsm + SWZ128((uint32_t)(t_row * 128 + t_c32 + 64));
        uint32_t s3 = dsm + SWZ128((uint32_t)(t_row * 128 + t_c32 + 80));
        cp_async16(s0, g);
        cp_async16(s1, g + 16);
        cp_async16(s2, g + 64);
        cp_async16(s3, g + 80);
    };
    auto load_step = [&](int kc, int s) {
        uint32_t sb = smem_base + s * STAGE;
        const size_t ko = (size_t)kc * 128;    // byte offset of hi chunk
        load_tile(Abase  + ko,        sb);             // Ah
        load_tile(Abase  + 2048 + ko, sb + 16384);     // Al
        load_tile(B0base + ko,        sb + 32768);     // B0h
        load_tile(B0base + 2048 + ko, sb + 49152);     // B0l
        if (ntiles == 2) {
            load_tile(B1base + ko,        sb + 65536); // B1h
            load_tile(B1base + 2048 + ko, sb + 81920); // B1l
        }
        CP_COMMIT();
    };

    load_step(0, 0);
    CP_WAIT0();
    __syncthreads();

    int phase0 = 0, phase1 = 0;
    for (int kc = 0; kc < NSTEP; ++kc) {
        const int s = kc & 1;
        if (wid == 0) {
            FENCE_PROXY_ASYNC();
            if (elect_one_pred()) {
                const uint32_t base = smem_base + s * STAGE;
                const uint64_t dAh = MAKE_SMEM_DESC(base);
                const uint64_t dAl = MAKE_SMEM_DESC(base + 16384);
                for (int t = 0; t < ntiles; ++t) {
                    const uint64_t dBh = MAKE_SMEM_DESC(base + 32768 + t * 32768);
                    const uint64_t dBl = MAKE_SMEM_DESC(base + 49152 + t * 32768);
                    const uint32_t dt = tmem_d + t * 128;
                    #pragma unroll
                    for (int j = 0; j < 4; ++j)
                        TCGEN05_MMA_F16_SS(dt, dAh + j * 2, dBh + j * 2, MMA_IDESC,
                                           (kc > 0) || (j > 0));
                    #pragma unroll
                    for (int j = 0; j < 4; ++j)
                        TCGEN05_MMA_F16_SS(dt, dAh + j * 2, dBl + j * 2, MMA_IDESC, true);
                    #pragma unroll
                    for (int j = 0; j < 4; ++j)
                        TCGEN05_MMA_F16_SS(dt, dAl + j * 2, dBh + j * 2, MMA_IDESC, true);
                }
                TCGEN05_COMMIT(s == 0 ? mbar0 : mbar1);
            }
        }
        if (kc + 1 < NSTEP) {
            const int s2 = (kc + 1) & 1;
            if (kc >= 1) {
                if (s2 == 0) { MBARRIER_WAIT_PARITY(mbar0, phase0); phase0 ^= 1; }
                else         { MBARRIER_WAIT_PARITY(mbar1, phase1); phase1 ^= 1; }
            }
            load_step(kc + 1, s2);
        }
        CP_WAIT0();
        __syncthreads();
    }
    // last step (kc=15) committed to mbar1
    MBARRIER_WAIT_PARITY(mbar1, phase1);
    TCGEN05_FENCE_AFTER();

    // epilogue: per D tile, warps 0-3 cols 0..63, warps 4-7 cols 64..127
    const int colbase = (wid >> 2) * 64;
    const int row = bm + (wid & 3) * 32 + (tid & 31);
    for (int t = 0; t < ntiles; ++t) {
        #pragma unroll
        for (int cb = 0; cb < 64; cb += 32) {
            uint32_t dr[32];
            TCGEN05_LD_X32(dr, tmem_d + t * 128 + colbase + cb);
            TCGEN05_WAIT_LD();
            TCGEN05_FENCE_BEFORE();
            #pragma unroll
            for (int c = 0; c < 32; c += 4) {
                const int col = bn + t * 128 + colbase + cb + c;
                float4 bs = *(const float4*)(bias + col);
                float4 o;
                o.x = scale * (__uint_as_float(dr[c + 0]) + bs.x);
                o.y = scale * (__uint_as_float(dr[c + 1]) + bs.y);
                o.z = scale * (__uint_as_float(dr[c + 2]) + bs.z);
                o.w = scale * (__uint_as_float(dr[c + 3]) + bs.w);
                if (RESID) {
                    float4 r = *(const float4*)(resid + (size_t)row * N + col);
                    o.x += r.x; o.y += r.y; o.z += r.z; o.w += r.w;
                }
                *(float4*)(out + (size_t)row * N + col) = o;
            }
        }
    }
    __syncthreads();
    if (tid == 0) { mbar_inval(mbar0); mbar_inval(mbar1); }
    __syncthreads();
    if (wid == 0) TCGEN05_DEALLOC(tmem_d, 256);
#else
    // Fallback for the compute_103 PTX pass (never run on sm_103a HW).
    const int tid = threadIdx.x;
    const int bm = blockIdx.y * 128;
    const int bn = blockIdx.x * 256;
    const int r0 = (tid >> 4) * 8;
    const int c0 = (tid & 15) * 8;
    for (int t = 0; t < ntiles; ++t)
    for (int i = 0; i < 8; ++i) {
        const int row = bm + r0 + i;
        const __nv_bfloat16* ar = A2 + (size_t)row * KSP2;
        for (int j = 0; j < 8; ++j) {
            const int col = bn + t * 128 + c0 + j;
            const __nv_bfloat16* br = B2 + (size_t)col * KSP2;
            float acc = 0.f;
            for (int k = 0; k < 1024; ++k) {
                float ah = __bfloat162float(ar[k]), al = __bfloat162float(ar[1024 + k]);
                float bh = __bfloat162float(br[k]), bl = __bfloat162float(br[1024 + k]);
                acc += ah * bh + ah * bl + al * bh;
            }
            float o = scale * (acc + bias[col]);
            if (RESID) o += resid[(size_t)row * N + col];
            out[(size_t)row * N + col] = o;
        }
    }
#endif
}

// ---------------- chunked scan, phase 1: per-chunk local scan (prefetched) --
__global__ void __launch_bounds__(256) scan_phase1_kernel() {
    const int tid = threadIdx.x;
    const int gid = blockIdx.x * 16 + (tid >> 4);   // 0..NSUM-1
    const int e = tid & 15;
    const int j = gid >> 9;          // chunk
    const int c = gid & 511;         // chain
    const int b = c >> 6, h = c & 63;
    const int t0 = j * CHUNK;

    size_t off = ((size_t)b * LL + t0) * DD + h * HDIM + e;
    size_t offIF = ((size_t)b * LL + t0) * (2 * HH);

    float C[16];
    #pragma unroll
    for (int d = 0; d < 16; ++d) C[d] = 0.f;
    float n = 0.f, m = -1e30f, F = 0.f;

    float ke = g_k[off], ve = g_v[off];
    float it = g_if[offIF + h], ft = g_if[offIF + HH + h];

    for (int t = 0; t < CHUNK; ++t) {
        const size_t off2 = off + DD;
        const size_t offIF2 = offIF + 2 * HH;
        float kn = ke, vn = ve, in_ = it, fn = ft;
        if (t + 1 < CHUNK) {
            kn = g_k[off2]; vn = g_v[off2];
            in_ = g_if[offIF2 + h]; fn = g_if[offIF2 + HH + h];
        }

        const float m_new = fmaxf(ft + m, it);
        const float fd = __expf(ft + m - m_new);
        const float id = __expf(it - m_new);
        m = m_new; F += ft;
        const float kid = id * ke;
        n = fd * n + kid;
        #pragma unroll
        for (int d = 0; d < 16; ++d) {
            const float vd = __shfl_sync(0xffffffffu, ve, d, 16);
            C[d] = fd * C[d] + vd * kid;
        }
        off = off2; offIF = offIF2;
        ke = kn; ve = vn; it = in_; ft = fn;
    }
    float* cs = g_Cloc + (size_t)gid * 256;
    #pragma unroll
    for (int d = 0; d < 16; ++d) cs[d * 16 + e] = C[d];
    g_nloc[(size_t)gid * 16 + e] = n;
    if (e == 0) { g_mloc[gid] = m; g_Floc[gid] = F; }
}

// ---------------- phase 2: serial combine across chunks (per chain) ---------
__global__ void __launch_bounds__(256) scan_phase2_kernel() {
    const int tid = threadIdx.x;
    const int c = blockIdx.x * 16 + (tid >> 4);     // chain 0..511
    const int e = tid & 15;

    float C[16];
    #pragma unroll
    for (int d = 0; d < 16; ++d) C[d] = 0.f;
    float n = 0.f, m = 0.f;                          // reference init: zeros

    for (int j = 0; j < NCH; ++j) {
        const int sid = j * NCHAINS + c;
        float* ci = g_Cin + (size_t)sid * 256;
        #pragma unroll
        for (int d = 0; d < 16; ++d) ci[d * 16 + e] = C[d];
        g_nin[(size_t)sid * 16 + e] = n;
        if (e == 0) g_min[sid] = m;
        const float ml = g_mloc[sid];
        const float F  = g_Floc[sid];
        const float mo = fmaxf(m + F, ml);
        const float a  = __expf(m + F - mo);
        const float bb = __expf(ml - mo);
        const float* cl = g_Cloc + (size_t)sid * 256;
        #pragma unroll
        for (int d = 0; d < 16; ++d) C[d] = a * C[d] + bb * cl[d * 16 + e];
        n = a * n + bb * g_nloc[(size_t)sid * 16 + e];
        m = mo;
    }
}

// ---------------- phase 3: replay chunk, emit h (prefetched) ----------------
__global__ void __launch_bounds__(256) scan_phase3_kernel() {
    const int tid = threadIdx.x;
    const int gid = blockIdx.x * 16 + (tid >> 4);
    const int e = tid & 15;
    const int j = gid >> 9;
    const int c = gid & 511;
    const int b = c >> 6, h = c & 63;
    const int t0 = j * CHUNK;

    size_t off = ((size_t)b * LL + t0) * DD + h * HDIM + e;
    size_t offIF = ((size_t)b * LL + t0) * (2 * HH);
    size_t h2off = ((size_t)b * LL + t0) * KSP2 + h * HDIM + e;

    const float* ci = g_Cin + (size_t)gid * 256;
    float C[16];
    #pragma unroll
    for (int d = 0; d < 16; ++d) C[d] = ci[d * 16 + e];
    float n = g_nin[(size_t)gid * 16 + e];
    float m = g_min[gid];

    float qe = g_q[off], ke = g_k[off], ve = g_v[off];
    float it = g_if[offIF + h], ft = g_if[offIF + HH + h];

    for (int t = 0; t < CHUNK; ++t) {
        const size_t off2 = off + DD;
        const size_t offIF2 = offIF + 2 * HH;
        float qn = qe, kn = ke, vn = ve, in_ = it, fn = ft;
        if (t + 1 < CHUNK) {
            qn = g_q[off2]; kn = g_k[off2]; vn = g_v[off2];
            in_ = g_if[offIF2 + h]; fn = g_if[offIF2 + HH + h];
        }

        const float m_new = fmaxf(ft + m, it);
        const float fd = __expf(ft + m - m_new);
        const float id = __expf(it - m_new);
        m = m_new;
        const float kid = id * ke;
        n = fd * n + kid;

        float cq = 0.f;
        #pragma unroll
        for (int d = 0; d < 16; ++d) {
            const float vd = __shfl_sync(0xffffffffu, ve, d, 16);
            const float qd = __shfl_sync(0xffffffffu, qe, d, 16);
            C[d] = fd * C[d] + vd * kid;
            cq = fmaf(C[d], qd, cq);
        }

        float nq = n * qe;
        #pragma unroll
        for (int o = 8; o; o >>= 1) nq += __shfl_xor_sync(0xffffffffu, nq, o, 16);
        const float denom = fmaxf(fabsf(nq), 1.0f);

        const float hval = cq / denom;
        __nv_bfloat16 hh, hl;
        split2(hval, hh, hl);
        g_h2[h2off] = hh;
        g_h2[h2off + 1024] = hl;

        off = off2; offIF = offIF2; h2off += KSP2;
        qe = qn; ke = kn; ve = vn; it = in_; ft = fn;
    }
}

// ---------------- launch ----------------------------------------------------
extern "C" void kernel_launch(void* const* d_in, const int* in_sizes, int n_in,
                              void* d_out, int out_size) {
    (void)in_sizes; (void)n_in; (void)out_size;
    const float* x     = (const float*)d_in[0];
    const float* gamma = (const float*)d_in[1];
    const float* beta  = (const float*)d_in[2];
    const float* qw    = (const float*)d_in[3];
    const float* qb    = (const float*)d_in[4];
    const float* kw    = (const float*)d_in[5];
    const float* kb    = (const float*)d_in[6];
    const float* vw    = (const float*)d_in[7];
    const float* vb    = (const float*)d_in[8];
    const float* ow    = (const float*)d_in[9];
    const float* ob    = (const float*)d_in[10];
    const float* iw    = (const float*)d_in[11];
    const float* ib    = (const float*)d_in[12];
    const float* fw    = (const float*)d_in[13];
    const float* fb    = (const float*)d_in[14];
    float* out = (float*)d_out;

    __nv_bfloat16 *a2, *h2, *qw2, *kw2, *vw2, *ow2, *wif2;
    float *qp, *kp, *vp, *ifp, *wif, *bif;
    cudaGetSymbolAddress((void**)&a2,   g_a2);
    cudaGetSymbolAddress((void**)&h2,   g_h2);
    cudaGetSymbolAddress((void**)&qw2,  g_qw2);
    cudaGetSymbolAddress((void**)&kw2,  g_kw2);
    cudaGetSymbolAddress((void**)&vw2,  g_vw2);
    cudaGetSymbolAddress((void**)&ow2,  g_ow2);
    cudaGetSymbolAddress((void**)&wif2, g_wif2);
    cudaGetSymbolAddress((void**)&qp,   g_q);
    cudaGetSymbolAddress((void**)&kp,   g_k);
    cudaGetSymbolAddress((void**)&vp,   g_v);
    cudaGetSymbolAddress((void**)&ifp,  g_if);
    cudaGetSymbolAddress((void**)&wif,  g_wif);
    cudaGetSymbolAddress((void**)&bif,  g_bif);

    cudaFuncSetAttribute(mma_gemm_kernel<false>,
                         cudaFuncAttributeMaxDynamicSharedMemorySize, SMEM_SZ);
    cudaFuncSetAttribute(mma_gemm_kernel<true>,
                         cudaFuncAttributeMaxDynamicSharedMemorySize, SMEM_SZ);

    // 1. LN + split
    ln_split_kernel<<<MROWS, 256>>>(x, gamma, beta);
    // 2. weight prep
    combine_if_kernel<<<(2 * HH * DD + 255) / 256, 256>>>(iw, ib, fw, fb);
    split_kernel<<<(DD * 256 + 255) / 256, 256>>>(qw, qw2, DD);
    split_kernel<<<(DD * 256 + 255) / 256, 256>>>(kw, kw2, DD);
    split_kernel<<<(DD * 256 + 255) / 256, 256>>>(vw, vw2, DD);
    split_kernel<<<(DD * 256 + 255) / 256, 256>>>(ow, ow2, DD);
    split_kernel<<<(2 * HH * 256 + 255) / 256, 256>>>(wif, wif2, 2 * HH);

    // 3. projections on tcgen05 (BM=128, BN=256)
    dim3 gridBig(DD / 256, MROWS / 128);   // (4, 256)
    dim3 gridIF(1, MROWS / 128);           // (1, 256), 1 N-tile
    mma_gemm_kernel<false><<<gridBig, 256, SMEM_SZ>>>(a2, qw2, qb, nullptr, qp, DD, 1.0f, 2);
    mma_gemm_kernel<false><<<gridBig, 256, SMEM_SZ>>>(a2, kw2, kb, nullptr, kp, DD, 0.25f, 2);
    mma_gemm_kernel<false><<<gridBig, 256, SMEM_SZ>>>(a2, vw2, vb, nullptr, vp, DD, 1.0f, 2);
    mma_gemm_kernel<false><<<gridIF, 256, SMEM_SZ>>>(a2, wif2, bif, nullptr, ifp, 2 * HH, 1.0f, 1);

    // 4. chunked parallel scan
    scan_phase1_kernel<<<NSUM / 16, 256>>>();
    scan_phase2_kernel<<<NCHAINS / 16, 256>>>();
    scan_phase3_kernel<<<NSUM / 16, 256>>>();

    // 5. output projection + residual
    mma_gemm_kernel<true><<<gridBig, 256, SMEM_SZ>>>(h2, ow2, ob, x, out, DD, 1.0f, 2);
}

// round 12
// speedup vs baseline: 1.5420x; 1.0003x over previous
#include <cuda_runtime.h>
#include <cuda_bf16.h>
#include <cstdint>
#include <math.h>

#define BB 8
#define LL 4096
#define DD 1024
#define HH 64
#define HDIM 16
#define MROWS (BB*LL)        // 32768
#define KSP2 2048            // [hi | lo] * 1024
#define ROWB 4096            // bytes per [hi|lo] row
#define NSTEP 16             // 1024/64 k-steps in GEMM

#define CHUNK 64
#define NCH (LL/CHUNK)       // 64 time-chunks
#define NCHAINS (BB*HH)      // 512
#define NSUM (NCH*NCHAINS)   // 32768

#define STAGE 98304          // 96KB: Ah,Al,B0h,B0l,B1h,B1l (16KB each)
#define SMEM_SZ (2*STAGE + 1024)

#if defined(__CUDA_ARCH__) && (__CUDA_ARCH__ == 1030) && defined(__CUDA_ARCH_FEAT_SM103_ALL)
#define HAS_TCGEN05 1
#else
#define HAS_TCGEN05 0
#endif

// ---------------- device scratch ------------------------------------------
__device__ __nv_bfloat16 g_a2[(size_t)MROWS * KSP2];   // split xn [hi|lo]
__device__ __nv_bfloat16 g_h2[(size_t)MROWS * KSP2];   // split hs [hi|lo]
__device__ float g_q [(size_t)MROWS * DD];
__device__ float g_k [(size_t)MROWS * DD];
__device__ float g_v [(size_t)MROWS * DD];
__device__ float g_if[(size_t)MROWS * 2 * HH];
__device__ __nv_bfloat16 g_qw2[(size_t)DD * KSP2];
__device__ __nv_bfloat16 g_kw2[(size_t)DD * KSP2];
__device__ __nv_bfloat16 g_vw2[(size_t)DD * KSP2];
__device__ __nv_bfloat16 g_ow2[(size_t)DD * KSP2];
__device__ __nv_bfloat16 g_wif2[(size_t)(2*HH) * KSP2];
__device__ float g_wif[2 * HH * DD];
__device__ float g_bif[2 * HH];
// chunked-scan summaries / entering states
__device__ float g_Cloc[(size_t)NSUM * 256];
__device__ float g_nloc[(size_t)NSUM * 16];
__device__ float g_mloc[NSUM];
__device__ float g_Floc[NSUM];
__device__ float g_Cin [(size_t)NSUM * 256];
__device__ float g_nin [(size_t)NSUM * 16];
__device__ float g_min [NSUM];

// ---------------- PTX helpers ------------------------------------------------
__device__ __forceinline__ uint32_t smem_u32(const void* p) {
    uint32_t a;
    asm("{ .reg .u64 t; cvta.to.shared.u64 t, %1; cvt.u32.u64 %0, t; }"
        : "=r"(a) : "l"(p));
    return a;
}

#if HAS_TCGEN05
__device__ __forceinline__ uint32_t elect_one_pred() {
    uint32_t pred;
    asm volatile("{\n\t.reg .pred p;\n\telect.sync _|p, 0xFFFFFFFF;\n\t"
                 "selp.b32 %0, 1, 0, p;\n\t}" : "=r"(pred));
    return pred;
}
#define TCGEN05_ALLOC(saddr, n) \
    asm volatile("tcgen05.alloc.cta_group::1.sync.aligned.shared::cta.b32 [%0], %1;" \
                 :: "r"((uint32_t)(saddr)), "r"((uint32_t)(n)) : "memory")
#define TCGEN05_DEALLOC(taddr, n) \
    asm volatile("tcgen05.dealloc.cta_group::1.sync.aligned.b32 %0, %1;" \
                 :: "r"(taddr), "r"((uint32_t)(n)))
#define TCGEN05_RELINQ() \
    asm volatile("tcgen05.relinquish_alloc_permit.cta_group::1.sync.aligned;")
#define TCGEN05_COMMIT(mbar) \
    asm volatile("tcgen05.commit.cta_group::1.mbarrier::arrive::one.shared::cluster.b64 [%0];" \
                 :: "r"((uint32_t)(mbar)) : "memory")
#define TCGEN05_FENCE_AFTER() \
    asm volatile("tcgen05.fence::after_thread_sync;" ::: "memory")
#define TCGEN05_FENCE_BEFORE() \
    asm volatile("tcgen05.fence::before_thread_sync;" ::: "memory")
#define TCGEN05_WAIT_LD() \
    asm volatile("tcgen05.wait::ld.sync.aligned;" ::: "memory")
#define FENCE_PROXY_ASYNC() \
    asm volatile("fence.proxy.async.shared::cta;" ::: "memory")
#define MBARRIER_INIT(mbar, cnt) \
    asm volatile("mbarrier.init.shared.b64 [%0], %1;" \
                 :: "r"((uint32_t)(mbar)), "r"((uint32_t)(cnt)) : "memory")
__device__ __forceinline__ void mbar_inval(uint32_t a) {
    asm volatile("mbarrier.inval.shared.b64 [%0];" :: "r"(a) : "memory");
}
#define MBARRIER_WAIT_PARITY(mbar, par) do { \
    uint32_t _m = (uint32_t)(mbar); uint32_t _p = (uint32_t)(par); uint32_t _d; \
    asm volatile("{\n\t.reg .pred p;\n\t" \
        "mbarrier.try_wait.parity.acquire.cta.shared::cta.b64 p, [%1], %2;\n\t" \
        "selp.b32 %0, 1, 0, p;\n\t}" : "=r"(_d) : "r"(_m), "r"(_p) : "memory"); \
    if (!_d) { \
        asm volatile("{\n\t.reg .pred P1;\n\t" \
            "WL_%=:\n\t" \
            "mbarrier.try_wait.parity.acquire.cta.shared::cta.b64 P1, [%0], %1, 0x989680;\n\t" \
            "@P1 bra.uni WD_%=;\n\tbra.uni WL_%=;\n\tWD_%=:\n\t}" \
            :: "r"(_m), "r"(_p) : "memory"); \
    } \
} while (0)
#define TCGEN05_MMA_F16_SS(dtm, adesc, bdesc, idesc, en) do { \
    uint32_t _e = (en) ? 1u : 0u; \
    asm volatile("{\n\t.reg .pred p;\n\tsetp.ne.u32 p, %5, 0;\n\t" \
        "tcgen05.mma.cta_group::1.kind::f16 [%0], %1, %2, %3, {%4, %4, %4, %4}, p;\n\t}" \
        :: "r"(dtm), "l"(adesc), "l"(bdesc), "r"(idesc), "r"(0u), "r"(_e) : "memory"); \
} while (0)
#define TCGEN05_LD_X32(r, taddr) \
    asm volatile("tcgen05.ld.sync.aligned.32x32b.x32.b32 " \
        "{%0, %1, %2, %3, %4, %5, %6, %7, %8, %9, %10, %11, %12, %13, %14, %15, " \
        "%16, %17, %18, %19, %20, %21, %22, %23, %24, %25, %26, %27, %28, %29, %30, %31}, [%32];" \
        : "=r"((r)[0]),  "=r"((r)[1]),  "=r"((r)[2]),  "=r"((r)[3]), \
          "=r"((r)[4]),  "=r"((r)[5]),  "=r"((r)[6]),  "=r"((r)[7]), \
          "=r"((r)[8]),  "=r"((r)[9]),  "=r"((r)[10]), "=r"((r)[11]), \
          "=r"((r)[12]), "=r"((r)[13]), "=r"((r)[14]), "=r"((r)[15]), \
          "=r"((r)[16]), "=r"((r)[17]), "=r"((r)[18]), "=r"((r)[19]), \
          "=r"((r)[20]), "=r"((r)[21]), "=r"((r)[22]), "=r"((r)[23]), \
          "=r"((r)[24]), "=r"((r)[25]), "=r"((r)[26]), "=r"((r)[27]), \
          "=r"((r)[28]), "=r"((r)[29]), "=r"((r)[30]), "=r"((r)[31]) \
        : "r"(taddr))

static constexpr uint64_t SMEM_DESC_BASE_SW128 =
    (uint64_t(2)  << 61) | (uint64_t(1) << 46) | (uint64_t(64) << 32) | (uint64_t(1) << 16);
#define MAKE_SMEM_DESC(a) (SMEM_DESC_BASE_SW128 | ((uint64_t)((a) >> 4) & 0x3FFF))

// idesc: f32 accum, bf16 A/B, M=128, N=128
static constexpr uint32_t MMA_IDESC =
    (1u << 4) | (1u << 7) | (1u << 10) | ((128u / 8) << 17) | ((128u / 16) << 24);
#endif  // HAS_TCGEN05

#define SWZ128(off) ((off) ^ (((off) >> 3) & 0x70))

// ---------------- bf16 split helper ----------------------------------------
__device__ __forceinline__ void split2(float v, __nv_bfloat16& hi, __nv_bfloat16& lo) {
    hi = __float2bfloat16(v);
    lo = __float2bfloat16(v - __bfloat162float(hi));
}

// ---------------- LayerNorm fused with [hi|lo] bf16 output ------------------
__global__ void ln_split_kernel(const float* __restrict__ x,
                                const float* __restrict__ gamma,
                                const float* __restrict__ beta) {
    __shared__ float s_sum[8], s_sq[8];
    const int row = blockIdx.x;
    const float4* xr = reinterpret_cast<const float4*>(x) + (size_t)row * (DD / 4);
    float4 v = xr[threadIdx.x];
    float s = v.x + v.y + v.z + v.w;
    float q = v.x * v.x + v.y * v.y + v.z * v.z + v.w * v.w;
    #pragma unroll
    for (int o = 16; o; o >>= 1) {
        s += __shfl_xor_sync(0xffffffffu, s, o);
        q += __shfl_xor_sync(0xffffffffu, q, o);
    }
    const int warp = threadIdx.x >> 5, lane = threadIdx.x & 31;
    if (lane == 0) { s_sum[warp] = s; s_sq[warp] = q; }
    __syncthreads();
    if (warp == 0) {
        s = (lane < 8) ? s_sum[lane] : 0.f;
        q = (lane < 8) ? s_sq[lane] : 0.f;
        #pragma unroll
        for (int o = 4; o; o >>= 1) {
            s += __shfl_xor_sync(0xffffffffu, s, o);
            q += __shfl_xor_sync(0xffffffffu, q, o);
        }
        if (lane == 0) { s_sum[0] = s; s_sq[0] = q; }
    }
    __syncthreads();
    const float mean = s_sum[0] * (1.f / DD);
    const float var  = s_sq[0] * (1.f / DD) - mean * mean;
    const float rstd = rsqrtf(var + 1e-5f);
    const float4 gg = reinterpret_cast<const float4*>(gamma)[threadIdx.x];
    const float4 bb = reinterpret_cast<const float4*>(beta)[threadIdx.x];
    float o0 = (v.x - mean) * rstd * gg.x + bb.x;
    float o1 = (v.y - mean) * rstd * gg.y + bb.y;
    float o2 = (v.z - mean) * rstd * gg.z + bb.z;
    float o3 = (v.w - mean) * rstd * gg.w + bb.w;
    __nv_bfloat16 h0, h1, h2, h3, l0, l1, l2, l3;
    split2(o0, h0, l0); split2(o1, h1, l1); split2(o2, h2, l2); split2(o3, h3, l3);
    __nv_bfloat16* dst = g_a2 + (size_t)row * KSP2 + threadIdx.x * 4;
    __nv_bfloat162 hA(h0, h1), hB(h2, h3), lA(l0, l1), lB(l2, l3);
    reinterpret_cast<__nv_bfloat162*>(dst)[0] = hA;
    reinterpret_cast<__nv_bfloat162*>(dst)[1] = hB;
    reinterpret_cast<__nv_bfloat162*>(dst + 1024)[0] = lA;
    reinterpret_cast<__nv_bfloat162*>(dst + 1024)[1] = lB;
}

// ---------------- generic fp32 -> [hi|lo] bf16 [rows,2048] ------------------
__global__ void split_kernel(const float* __restrict__ src, __nv_bfloat16* __restrict__ dst,
                             int rows) {
    int i = blockIdx.x * blockDim.x + threadIdx.x;
    if (i >= rows * 256) return;
    int row = i >> 8;
    int g = i & 255;
    float4 v = reinterpret_cast<const float4*>(src + (size_t)row * DD)[g];
    __nv_bfloat16 h0, h1, h2, h3, l0, l1, l2, l3;
    split2(v.x, h0, l0); split2(v.y, h1, l1); split2(v.z, h2, l2); split2(v.w, h3, l3);
    __nv_bfloat16* d = dst + (size_t)row * KSP2 + g * 4;
    __nv_bfloat162 hA(h0, h1), hB(h2, h3), lA(l0, l1), lB(l2, l3);
    reinterpret_cast<__nv_bfloat162*>(d)[0] = hA;
    reinterpret_cast<__nv_bfloat162*>(d)[1] = hB;
    reinterpret_cast<__nv_bfloat162*>(d + 1024)[0] = lA;
    reinterpret_cast<__nv_bfloat162*>(d + 1024)[1] = lB;
}

// ---------------- pack i/f weights -----------------------------------------
__global__ void combine_if_kernel(const float* __restrict__ iw,
                                  const float* __restrict__ ib,
                                  const float* __restrict__ fw,
                                  const float* __restrict__ fb) {
    int idx = blockIdx.x * blockDim.x + threadIdx.x;
    if (idx < 2 * HH * DD) {
        int nrow = idx / DD;
        g_wif[idx] = (nrow < HH) ? iw[idx] : fw[idx - HH * DD];
    }
    if (idx < 2 * HH) g_bif[idx] = (idx < HH) ? ib[idx] : fb[idx - HH];
}

// ---------------- tcgen05 GEMM (round-7 geometry, LDG+STS loads) ------------
// out[m,n] = scale*(Ah·Bh + Ah·Bl + Al·Bh + bias) (+resid)
template <bool RESID>
__global__ void __launch_bounds__(256, 1) mma_gemm_kernel(
    const __nv_bfloat16* __restrict__ A2,
    const __nv_bfloat16* __restrict__ B2,
    const float* __restrict__ bias,
    const float* __restrict__ resid,
    float* __restrict__ out,
    int N, float scale, int ntiles)
{
#if HAS_TCGEN05
    extern __shared__ char smem_raw[];
    char* smem = (char*)(((uintptr_t)smem_raw + 1023) & ~(uintptr_t)1023);
    __shared__ __align__(16) uint64_t s_mbar[2];
    __shared__ uint32_t s_tmem;

    const int tid = threadIdx.x;
    const int wid = tid >> 5;
    const int bm = blockIdx.y * 128;
    const int bn = blockIdx.x * 256;      // 2 tiles of 128 (ntiles==2)
    const uint32_t smem_base = smem_u32(smem);

    if (wid == 0) {
        TCGEN05_ALLOC(smem_u32(&s_tmem), 256);
        TCGEN05_RELINQ();
    }
    if (tid == 0) {
        MBARRIER_INIT(smem_u32(&s_mbar[0]), 1);
        MBARRIER_INIT(smem_u32(&s_mbar[1]), 1);
    }
    __syncthreads();
    const uint32_t tmem_d = s_tmem;
    const uint32_t mbar0 = smem_u32(&s_mbar[0]);
    const uint32_t mbar1 = smem_u32(&s_mbar[1]);

    const char* Abase  = (const char*)(A2 + (size_t)bm * KSP2);
    const char* B0base = (const char*)(B2 + (size_t)bn * KSP2);
    const char* B1base = B0base + (size_t)128 * ROWB;

    auto load_tile = [&](const char* src, char* dst) {
        #pragma unroll
        for (int i = 0; i < 4; ++i) {
            int cidx = tid + i * 256;
            int row = cidx >> 3;
            int c16 = cidx & 7;
            uint4 v = *(const uint4*)(src + (size_t)row * ROWB + c16 * 16);
            *(uint4*)(dst + SWZ128(row * 128 + c16 * 16)) = v;
        }
    };
    auto load_step = [&](int kc, int s) {
        char* sb = smem + s * STAGE;
        const size_t ko = (size_t)kc * 128;    // byte offset of hi chunk
        load_tile(Abase  + ko,        sb);             // Ah
        load_tile(Abase  + 2048 + ko, sb + 16384);     // Al
        load_tile(B0base + ko,        sb + 32768);     // B0h
        load_tile(B0base + 2048 + ko, sb + 49152);     // B0l
        if (ntiles == 2) {
            load_tile(B1base + ko,        sb + 65536); // B1h
            load_tile(B1base + 2048 + ko, sb + 81920); // B1l
        }
    };

    load_step(0, 0);
    __syncthreads();

    int phase0 = 0, phase1 = 0;
    for (int kc = 0; kc < NSTEP; ++kc) {
        const int s = kc & 1;
        if (wid == 0) {
            FENCE_PROXY_ASYNC();
            if (elect_one_pred()) {
                const uint32_t base = smem_base + s * STAGE;
                const uint64_t dAh = MAKE_SMEM_DESC(base);
                const uint64_t dAl = MAKE_SMEM_DESC(base + 16384);
                for (int t = 0; t < ntiles; ++t) {
                    const uint64_t dBh = MAKE_SMEM_DESC(base + 32768 + t * 32768);
                    const uint64_t dBl = MAKE_SMEM_DESC(base + 49152 + t * 32768);
                    const uint32_t dt = tmem_d + t * 128;
                    #pragma unroll
                    for (int j = 0; j < 4; ++j)
                        TCGEN05_MMA_F16_SS(dt, dAh + j * 2, dBh + j * 2, MMA_IDESC,
                                           (kc > 0) || (j > 0));
                    #pragma unroll
                    for (int j = 0; j < 4; ++j)
                        TCGEN05_MMA_F16_SS(dt, dAh + j * 2, dBl + j * 2, MMA_IDESC, true);
                    #pragma unroll
                    for (int j = 0; j < 4; ++j)
                        TCGEN05_MMA_F16_SS(dt, dAl + j * 2, dBh + j * 2, MMA_IDESC, true);
                }
                TCGEN05_COMMIT(s == 0 ? mbar0 : mbar1);
            }
        }
        if (kc + 1 < NSTEP) {
            const int s2 = (kc + 1) & 1;
            if (kc >= 1) {
                if (s2 == 0) { MBARRIER_WAIT_PARITY(mbar0, phase0); phase0 ^= 1; }
                else         { MBARRIER_WAIT_PARITY(mbar1, phase1); phase1 ^= 1; }
            }
            load_step(kc + 1, s2);
        }
        __syncthreads();
    }
    // last step (kc=15) committed to mbar1
    MBARRIER_WAIT_PARITY(mbar1, phase1);
    TCGEN05_FENCE_AFTER();

    // epilogue: per D tile, warps 0-3 cols 0..63, warps 4-7 cols 64..127
    const int colbase = (wid >> 2) * 64;
    const int row = bm + (wid & 3) * 32 + (tid & 31);
    for (int t = 0; t < ntiles; ++t) {
        #pragma unroll
        for (int cb = 0; cb < 64; cb += 32) {
            uint32_t dr[32];
            TCGEN05_LD_X32(dr, tmem_d + t * 128 + colbase + cb);
            TCGEN05_WAIT_LD();
            TCGEN05_FENCE_BEFORE();
            #pragma unroll
            for (int c = 0; c < 32; c += 4) {
                const int col = bn + t * 128 + colbase + cb + c;
                float4 bs = *(const float4*)(bias + col);
                float4 o;
                o.x = scale * (__uint_as_float(dr[c + 0]) + bs.x);
                o.y = scale * (__uint_as_float(dr[c + 1]) + bs.y);
                o.z = scale * (__uint_as_float(dr[c + 2]) + bs.z);
                o.w = scale * (__uint_as_float(dr[c + 3]) + bs.w);
                if (RESID) {
                    float4 r = *(const float4*)(resid + (size_t)row * N + col);
                    o.x += r.x; o.y += r.y; o.z += r.z; o.w += r.w;
                }
                *(float4*)(out + (size_t)row * N + col) = o;
            }
        }
    }
    __syncthreads();
    if (tid == 0) { mbar_inval(mbar0); mbar_inval(mbar1); }
    __syncthreads();
    if (wid == 0) TCGEN05_DEALLOC(tmem_d, 256);
#else
    // Fallback for the compute_103 PTX pass (never run on sm_103a HW).
    const int tid = threadIdx.x;
    const int bm = blockIdx.y * 128;
    const int bn = blockIdx.x * 256;
    const int r0 = (tid >> 4) * 8;
    const int c0 = (tid & 15) * 8;
    for (int t = 0; t < ntiles; ++t)
    for (int i = 0; i < 8; ++i) {
        const int row = bm + r0 + i;
        const __nv_bfloat16* ar = A2 + (size_t)row * KSP2;
        for (int j = 0; j < 8; ++j) {
            const int col = bn + t * 128 + c0 + j;
            const __nv_bfloat16* br = B2 + (size_t)col * KSP2;
            float acc = 0.f;
            for (int k = 0; k < 1024; ++k) {
                float ah = __bfloat162float(ar[k]), al = __bfloat162float(ar[1024 + k]);
                float bh = __bfloat162float(br[k]), bl = __bfloat162float(br[1024 + k]);
                acc += ah * bh + ah * bl + al * bh;
            }
            float o = scale * (acc + bias[col]);
            if (RESID) o += resid[(size_t)row * N + col];
            out[(size_t)row * N + col] = o;
        }
    }
#endif
}

// ---------------- chunked scan, phase 1: de-SHFLed local scan ---------------
// 16 lanes per (chain, chunk); lane e holds C[:, e]. v row loaded via float4
// broadcast (L1) instead of 16 shuffles.
__global__ void __launch_bounds__(256) scan_phase1_kernel() {
    const int tid = threadIdx.x;
    const int gid = blockIdx.x * 16 + (tid >> 4);   // 0..NSUM-1
    const int e = tid & 15;
    const int j = gid >> 9;          // chunk
    const int c = gid & 511;         // chain
    const int b = c >> 6, h = c & 63;
    const int t0 = j * CHUNK;

    size_t rowoff = ((size_t)b * LL + t0) * DD + h * HDIM;   // row base (16 floats)
    size_t offIF = ((size_t)b * LL + t0) * (2 * HH);

    float C[16];
    #pragma unroll
    for (int d = 0; d < 16; ++d) C[d] = 0.f;
    float n = 0.f, m = -1e30f, F = 0.f;

    for (int t = 0; t < CHUNK; ++t) {
        const float4* vr4 = reinterpret_cast<const float4*>(g_v + rowoff);
        float4 v0 = vr4[0], v1 = vr4[1], v2 = vr4[2], v3 = vr4[3];
        const float ke = g_k[rowoff + e];
        const float it = g_if[offIF + h];
        const float ft = g_if[offIF + HH + h];

        const float m_new = fmaxf(ft + m, it);
        const float fd = __expf(ft + m - m_new);
        const float id = __expf(it - m_new);
        m = m_new; F += ft;
        const float kid = id * ke;
        n = fd * n + kid;

        float vr[16] = {v0.x, v0.y, v0.z, v0.w, v1.x, v1.y, v1.z, v1.w,
                        v2.x, v2.y, v2.z, v2.w, v3.x, v3.y, v3.z, v3.w};
        #pragma unroll
        for (int d = 0; d < 16; ++d)
            C[d] = fd * C[d] + vr[d] * kid;

        rowoff += DD; offIF += 2 * HH;
    }
    float* cs = g_Cloc + (size_t)gid * 256;
    #pragma unroll
    for (int d = 0; d < 16; ++d) cs[d * 16 + e] = C[d];
    g_nloc[(size_t)gid * 16 + e] = n;
    if (e == 0) { g_mloc[gid] = m; g_Floc[gid] = F; }
}

// ---------------- phase 2: serial combine across chunks (per chain) ---------
__global__ void __launch_bounds__(256) scan_phase2_kernel() {
    const int tid = threadIdx.x;
    const int c = blockIdx.x * 16 + (tid >> 4);     // chain 0..511
    const int e = tid & 15;

    float C[16];
    #pragma unroll
    for (int d = 0; d < 16; ++d) C[d] = 0.f;
    float n = 0.f, m = 0.f;                          // reference init: zeros

    for (int j = 0; j < NCH; ++j) {
        const int sid = j * NCHAINS + c;
        float* ci = g_Cin + (size_t)sid * 256;
        #pragma unroll
        for (int d = 0; d < 16; ++d) ci[d * 16 + e] = C[d];
        g_nin[(size_t)sid * 16 + e] = n;
        if (e == 0) g_min[sid] = m;
        const float ml = g_mloc[sid];
        const float F  = g_Floc[sid];
        const float mo = fmaxf(m + F, ml);
        const float a  = __expf(m + F - mo);
        const float bb = __expf(ml - mo);
        const float* cl = g_Cloc + (size_t)sid * 256;
        #pragma unroll
        for (int d = 0; d < 16; ++d) C[d] = a * C[d] + bb * cl[d * 16 + e];
        n = a * n + bb * g_nloc[(size_t)sid * 16 + e];
        m = mo;
    }
}

// ---------------- phase 3: de-SHFLed replay, emit h -------------------------
__global__ void __launch_bounds__(256) scan_phase3_kernel() {
    const int tid = threadIdx.x;
    const int gid = blockIdx.x * 16 + (tid >> 4);
    const int e = tid & 15;
    const int j = gid >> 9;
    const int c = gid & 511;
    const int b = c >> 6, h = c & 63;
    const int t0 = j * CHUNK;

    size_t rowoff = ((size_t)b * LL + t0) * DD + h * HDIM;
    size_t offIF = ((size_t)b * LL + t0) * (2 * HH);
    size_t h2off = ((size_t)b * LL + t0) * KSP2 + h * HDIM + e;

    const float* ci = g_Cin + (size_t)gid * 256;
    float C[16];
    #pragma unroll
    for (int d = 0; d < 16; ++d) C[d] = ci[d * 16 + e];
    float n = g_nin[(size_t)gid * 16 + e];
    float m = g_min[gid];

    for (int t = 0; t < CHUNK; ++t) {
        const float4* vr4 = reinterpret_cast<const float4*>(g_v + rowoff);
        const float4* qr4 = reinterpret_cast<const float4*>(g_q + rowoff);
        float4 v0 = vr4[0], v1 = vr4[1], v2 = vr4[2], v3 = vr4[3];
        float4 q0 = qr4[0], q1 = qr4[1], q2 = qr4[2], q3 = qr4[3];
        const float ke = g_k[rowoff + e];
        const float qe = g_q[rowoff + e];
        const float it = g_if[offIF + h];
        const float ft = g_if[offIF + HH + h];

        const float m_new = fmaxf(ft + m, it);
        const float fd = __expf(ft + m - m_new);
        const float id = __expf(it - m_new);
        m = m_new;
        const float kid = id * ke;
        n = fd * n + kid;

        float vr[16] = {v0.x, v0.y, v0.z, v0.w, v1.x, v1.y, v1.z, v1.w,
                        v2.x, v2.y, v2.z, v2.w, v3.x, v3.y, v3.z, v3.w};
        float qr[16] = {q0.x, q0.y, q0.z, q0.w, q1.x, q1.y, q1.z, q1.w,
                        q2.x, q2.y, q2.z, q2.w, q3.x, q3.y, q3.z, q3.w};
        float cq = 0.f;
        #pragma unroll
        for (int d = 0; d < 16; ++d) {
            C[d] = fd * C[d] + vr[d] * kid;
            cq = fmaf(C[d], qr[d], cq);
        }

        float nq = n * qe;
        #pragma unroll
        for (int o = 8; o; o >>= 1) nq += __shfl_xor_sync(0xffffffffu, nq, o, 16);
        const float denom = fmaxf(fabsf(nq), 1.0f);

        const float hval = cq / denom;
        __nv_bfloat16 hh, hl;
        split2(hval, hh, hl);
        g_h2[h2off] = hh;
        g_h2[h2off + 1024] = hl;

        rowoff += DD; offIF += 2 * HH; h2off += KSP2;
    }
}

// ---------------- launch ----------------------------------------------------
extern "C" void kernel_launch(void* const* d_in, const int* in_sizes, int n_in,
                              void* d_out, int out_size) {
    (void)in_sizes; (void)n_in; (void)out_size;
    const float* x     = (const float*)d_in[0];
    const float* gamma = (const float*)d_in[1];
    const float* beta  = (const float*)d_in[2];
    const float* qw    = (const float*)d_in[3];
    const float* qb    = (const float*)d_in[4];
    const float* kw    = (const float*)d_in[5];
    const float* kb    = (const float*)d_in[6];
    const float* vw    = (const float*)d_in[7];
    const float* vb    = (const float*)d_in[8];
    const float* ow    = (const float*)d_in[9];
    const float* ob    = (const float*)d_in[10];
    const float* iw    = (const float*)d_in[11];
    const float* ib    = (const float*)d_in[12];
    const float* fw    = (const float*)d_in[13];
    const float* fb    = (const float*)d_in[14];
    float* out = (float*)d_out;

    __nv_bfloat16 *a2, *h2, *qw2, *kw2, *vw2, *ow2, *wif2;
    float *qp, *kp, *vp, *ifp, *wif, *bif;
    cudaGetSymbolAddress((void**)&a2,   g_a2);
    cudaGetSymbolAddress((void**)&h2,   g_h2);
    cudaGetSymbolAddress((void**)&qw2,  g_qw2);
    cudaGetSymbolAddress((void**)&kw2,  g_kw2);
    cudaGetSymbolAddress((void**)&vw2,  g_vw2);
    cudaGetSymbolAddress((void**)&ow2,  g_ow2);
    cudaGetSymbolAddress((void**)&wif2, g_wif2);
    cudaGetSymbolAddress((void**)&qp,   g_q);
    cudaGetSymbolAddress((void**)&kp,   g_k);
    cudaGetSymbolAddress((void**)&vp,   g_v);
    cudaGetSymbolAddress((void**)&ifp,  g_if);
    cudaGetSymbolAddress((void**)&wif,  g_wif);
    cudaGetSymbolAddress((void**)&bif,  g_bif);

    cudaFuncSetAttribute(mma_gemm_kernel<false>,
                         cudaFuncAttributeMaxDynamicSharedMemorySize, SMEM_SZ);
    cudaFuncSetAttribute(mma_gemm_kernel<true>,
                         cudaFuncAttributeMaxDynamicSharedMemorySize, SMEM_SZ);

    // 1. LN + split
    ln_split_kernel<<<MROWS, 256>>>(x, gamma, beta);
    // 2. weight prep
    combine_if_kernel<<<(2 * HH * DD + 255) / 256, 256>>>(iw, ib, fw, fb);
    split_kernel<<<(DD * 256 + 255) / 256, 256>>>(qw, qw2, DD);
    split_kernel<<<(DD * 256 + 255) / 256, 256>>>(kw, kw2, DD);
    split_kernel<<<(DD * 256 + 255) / 256, 256>>>(vw, vw2, DD);
    split_kernel<<<(DD * 256 + 255) / 256, 256>>>(ow, ow2, DD);
    split_kernel<<<(2 * HH * 256 + 255) / 256, 256>>>(wif, wif2, 2 * HH);

    // 3. projections on tcgen05 (BM=128, BN=256)
    dim3 gridBig(DD / 256, MROWS / 128);   // (4, 256)
    dim3 gridIF(1, MROWS / 128);           // (1, 256), 1 N-tile
    mma_gemm_kernel<false><<<gridBig, 256, SMEM_SZ>>>(a2, qw2, qb, nullptr, qp, DD, 1.0f, 2);
    mma_gemm_kernel<false><<<gridBig, 256, SMEM_SZ>>>(a2, kw2, kb, nullptr, kp, DD, 0.25f, 2);
    mma_gemm_kernel<false><<<gridBig, 256, SMEM_SZ>>>(a2, vw2, vb, nullptr, vp, DD, 1.0f, 2);
    mma_gemm_kernel<false><<<gridIF, 256, SMEM_SZ>>>(a2, wif2, bif, nullptr, ifp, 2 * HH, 1.0f, 1);

    // 4. chunked parallel scan
    scan_phase1_kernel<<<NSUM / 16, 256>>>();
    scan_phase2_kernel<<<NCHAINS / 16, 256>>>();
    scan_phase3_kernel<<<NSUM / 16, 256>>>();

    // 5. output projection + residual
    mma_gemm_kernel<true><<<gridBig, 256, SMEM_SZ>>>(h2, ow2, ob, x, out, DD, 1.0f, 2);
}

// round 13
// speedup vs baseline: 1.6631x; 1.0785x over previous
#include <cuda_runtime.h>
#include <cuda_bf16.h>
#include <cstdint>
#include <math.h>

#define BB 8
#define LL 4096
#define DD 1024
#define HH 64
#define HDIM 16
#define MROWS (BB*LL)        // 32768
#define KSP2 2048            // [hi | lo] * 1024
#define ROWB 4096            // bytes per [hi|lo] row
#define NSTEP 16             // 1024/64 k-steps in GEMM

#define CHUNK 64
#define NCH (LL/CHUNK)       // 64 time-chunks
#define NCHAINS (BB*HH)      // 512
#define NSUM (NCH*NCHAINS)   // 32768

#define STAGE 98304          // 96KB per stage (6 x 16KB tiles)
#define SMEM_SZ (2*STAGE + 1024)

#if defined(__CUDA_ARCH__) && (__CUDA_ARCH__ == 1030) && defined(__CUDA_ARCH_FEAT_SM103_ALL)
#define HAS_TCGEN05 1
#else
#define HAS_TCGEN05 0
#endif

// ---------------- device scratch ------------------------------------------
__device__ __nv_bfloat16 g_a2[(size_t)MROWS * KSP2];   // split xn [hi|lo]
__device__ __nv_bfloat16 g_h2[(size_t)MROWS * KSP2];   // split hs [hi|lo]
__device__ float g_q [(size_t)MROWS * DD];
__device__ float g_k [(size_t)MROWS * DD];
__device__ float g_v [(size_t)MROWS * DD];
__device__ float g_if[(size_t)MROWS * 2 * HH];
__device__ __nv_bfloat16 g_qw2[(size_t)DD * KSP2];
__device__ __nv_bfloat16 g_kw2[(size_t)DD * KSP2];
__device__ __nv_bfloat16 g_vw2[(size_t)DD * KSP2];
__device__ __nv_bfloat16 g_ow2[(size_t)DD * KSP2];
__device__ __nv_bfloat16 g_wif2[(size_t)(2*HH) * KSP2];
__device__ float g_wif[2 * HH * DD];
__device__ float g_bif[2 * HH];
// chunked-scan summaries / entering states
__device__ float g_Cloc[(size_t)NSUM * 256];
__device__ float g_nloc[(size_t)NSUM * 16];
__device__ float g_mloc[NSUM];
__device__ float g_Floc[NSUM];
__device__ float g_Cin [(size_t)NSUM * 256];
__device__ float g_nin [(size_t)NSUM * 16];
__device__ float g_min [NSUM];

// ---------------- PTX helpers ------------------------------------------------
__device__ __forceinline__ uint32_t smem_u32(const void* p) {
    uint32_t a;
    asm("{ .reg .u64 t; cvta.to.shared.u64 t, %1; cvt.u32.u64 %0, t; }"
        : "=r"(a) : "l"(p));
    return a;
}
__device__ __forceinline__ uint32_t cluster_rank() {
    uint32_t r;
    asm("mov.u32 %0, %%cluster_ctarank;" : "=r"(r));
    return r;
}
#define CLUSTER_SYNC() do { \
    asm volatile("barrier.cluster.arrive.aligned;" ::: "memory"); \
    asm volatile("barrier.cluster.wait.aligned;" ::: "memory"); \
} while (0)

#if HAS_TCGEN05
__device__ __forceinline__ uint32_t elect_one_pred() {
    uint32_t pred;
    asm volatile("{\n\t.reg .pred p;\n\telect.sync _|p, 0xFFFFFFFF;\n\t"
                 "selp.b32 %0, 1, 0, p;\n\t}" : "=r"(pred));
    return pred;
}
#define TCGEN05_ALLOC(saddr, n) \
    asm volatile("tcgen05.alloc.cta_group::1.sync.aligned.shared::cta.b32 [%0], %1;" \
                 :: "r"((uint32_t)(saddr)), "r"((uint32_t)(n)) : "memory")
#define TCGEN05_DEALLOC(taddr, n) \
    asm volatile("tcgen05.dealloc.cta_group::1.sync.aligned.b32 %0, %1;" \
                 :: "r"(taddr), "r"((uint32_t)(n)))
#define TCGEN05_RELINQ() \
    asm volatile("tcgen05.relinquish_alloc_permit.cta_group::1.sync.aligned;")
#define TCGEN05_ALLOC_CG2(saddr, n) \
    asm volatile("tcgen05.alloc.cta_group::2.sync.aligned.shared::cta.b32 [%0], %1;" \
                 :: "r"((uint32_t)(saddr)), "r"((uint32_t)(n)) : "memory")
#define TCGEN05_DEALLOC_CG2(taddr, n) \
    asm volatile("tcgen05.dealloc.cta_group::2.sync.aligned.b32 %0, %1;" \
                 :: "r"(taddr), "r"((uint32_t)(n)))
#define TCGEN05_RELINQ_CG2() \
    asm volatile("tcgen05.relinquish_alloc_permit.cta_group::2.sync.aligned;")
#define TCGEN05_COMMIT(mbar) \
    asm volatile("tcgen05.commit.cta_group::1.mbarrier::arrive::one.shared::cluster.b64 [%0];" \
                 :: "r"((uint32_t)(mbar)) : "memory")
#define TCGEN05_COMMIT_MC_CG2(mbar, mask) \
    asm volatile("tcgen05.commit.cta_group::2.mbarrier::arrive::one.shared::cluster.multicast::cluster.b64 [%0], %1;" \
                 :: "r"((uint32_t)(mbar)), "h"((uint16_t)(mask)) : "memory")
#define TCGEN05_FENCE_AFTER() \
    asm volatile("tcgen05.fence::after_thread_sync;" ::: "memory")
#define TCGEN05_FENCE_BEFORE() \
    asm volatile("tcgen05.fence::before_thread_sync;" ::: "memory")
#define TCGEN05_WAIT_LD() \
    asm volatile("tcgen05.wait::ld.sync.aligned;" ::: "memory")
#define FENCE_PROXY_ASYNC() \
    asm volatile("fence.proxy.async.shared::cta;" ::: "memory")
#define FENCE_PROXY_ASYNC_ALL() \
    asm volatile("fence.proxy.async;" ::: "memory")
#define MBARRIER_INIT(mbar, cnt) \
    asm volatile("mbarrier.init.shared.b64 [%0], %1;" \
                 :: "r"((uint32_t)(mbar)), "r"((uint32_t)(cnt)) : "memory")
#define MBARRIER_ARRIVE_LOCAL(mbar) \
    asm volatile("mbarrier.arrive.shared.b64 _, [%0];" :: "r"((uint32_t)(mbar)) : "memory")
#define MBARRIER_ARRIVE_CLUSTER(addr, rankv) \
    asm volatile("{\n\t.reg .b32 ra;\n\tmapa.shared::cluster.u32 ra, %0, %1;\n\t" \
        "mbarrier.arrive.shared::cluster.b64 _, [ra];\n\t}" \
        :: "r"((uint32_t)(addr)), "r"((uint32_t)(rankv)) : "memory")
__device__ __forceinline__ void mbar_inval(uint32_t a) {
    asm volatile("mbarrier.inval.shared.b64 [%0];" :: "r"(a) : "memory");
}
#define MBARRIER_WAIT_PARITY(mbar, par) do { \
    uint32_t _m = (uint32_t)(mbar); uint32_t _p = (uint32_t)(par); uint32_t _d; \
    asm volatile("{\n\t.reg .pred p;\n\t" \
        "mbarrier.try_wait.parity.acquire.cta.shared::cta.b64 p, [%1], %2;\n\t" \
        "selp.b32 %0, 1, 0, p;\n\t}" : "=r"(_d) : "r"(_m), "r"(_p) : "memory"); \
    if (!_d) { \
        asm volatile("{\n\t.reg .pred P1;\n\t" \
            "WL_%=:\n\t" \
            "mbarrier.try_wait.parity.acquire.cta.shared::cta.b64 P1, [%0], %1, 0x989680;\n\t" \
            "@P1 bra.uni WD_%=;\n\tbra.uni WL_%=;\n\tWD_%=:\n\t}" \
            :: "r"(_m), "r"(_p) : "memory"); \
    } \
} while (0)
#define TCGEN05_MMA_F16_SS(dtm, adesc, bdesc, idesc, en) do { \
    uint32_t _e = (en) ? 1u : 0u; \
    asm volatile("{\n\t.reg .pred p;\n\tsetp.ne.u32 p, %5, 0;\n\t" \
        "tcgen05.mma.cta_group::1.kind::f16 [%0], %1, %2, %3, {%4, %4, %4, %4}, p;\n\t}" \
        :: "r"(dtm), "l"(adesc), "l"(bdesc), "r"(idesc), "r"(0u), "r"(_e) : "memory"); \
} while (0)
#define TCGEN05_MMA_F16_SS_CG2(dtm, adesc, bdesc, idesc, en) do { \
    uint32_t _e = (en) ? 1u : 0u; \
    asm volatile("{\n\t.reg .pred p;\n\tsetp.ne.u32 p, %5, 0;\n\t" \
        "tcgen05.mma.cta_group::2.kind::f16 [%0], %1, %2, %3, {%4,%4,%4,%4,%4,%4,%4,%4}, p;\n\t}" \
        :: "r"(dtm), "l"(adesc), "l"(bdesc), "r"(idesc), "r"(0u), "r"(_e) : "memory"); \
} while (0)
#define TCGEN05_LD_X32(r, taddr) \
    asm volatile("tcgen05.ld.sync.aligned.32x32b.x32.b32 " \
        "{%0, %1, %2, %3, %4, %5, %6, %7, %8, %9, %10, %11, %12, %13, %14, %15, " \
        "%16, %17, %18, %19, %20, %21, %22, %23, %24, %25, %26, %27, %28, %29, %30, %31}, [%32];" \
        : "=r"((r)[0]),  "=r"((r)[1]),  "=r"((r)[2]),  "=r"((r)[3]), \
          "=r"((r)[4]),  "=r"((r)[5]),  "=r"((r)[6]),  "=r"((r)[7]), \
          "=r"((r)[8]),  "=r"((r)[9]),  "=r"((r)[10]), "=r"((r)[11]), \
          "=r"((r)[12]), "=r"((r)[13]), "=r"((r)[14]), "=r"((r)[15]), \
          "=r"((r)[16]), "=r"((r)[17]), "=r"((r)[18]), "=r"((r)[19]), \
          "=r"((r)[20]), "=r"((r)[21]), "=r"((r)[22]), "=r"((r)[23]), \
          "=r"((r)[24]), "=r"((r)[25]), "=r"((r)[26]), "=r"((r)[27]), \
          "=r"((r)[28]), "=r"((r)[29]), "=r"((r)[30]), "=r"((r)[31]) \
        : "r"(taddr))

static constexpr uint64_t SMEM_DESC_BASE_SW128 =
    (uint64_t(2)  << 61) | (uint64_t(1) << 46) | (uint64_t(64) << 32) | (uint64_t(1) << 16);
#define MAKE_SMEM_DESC(a) (SMEM_DESC_BASE_SW128 | ((uint64_t)((a) >> 4) & 0x3FFF))

// idesc: f32 accum, bf16 A/B
static constexpr uint32_t MMA_IDESC =       // M=128, N=128 (cg1)
    (1u << 4) | (1u << 7) | (1u << 10) | ((128u / 8) << 17) | ((128u / 16) << 24);
static constexpr uint32_t MMA_IDESC2 =      // M=256, N=256 (cg2)
    (1u << 4) | (1u << 7) | (1u << 10) | ((256u / 8) << 17) | ((256u / 16) << 24);
#endif  // HAS_TCGEN05

#define SWZ128(off) ((off) ^ (((off) >> 3) & 0x70))

// ---------------- bf16 split helper ----------------------------------------
__device__ __forceinline__ void split2(float v, __nv_bfloat16& hi, __nv_bfloat16& lo) {
    hi = __float2bfloat16(v);
    lo = __float2bfloat16(v - __bfloat162float(hi));
}

// ---------------- LayerNorm fused with [hi|lo] bf16 output ------------------
__global__ void ln_split_kernel(const float* __restrict__ x,
                                const float* __restrict__ gamma,
                                const float* __restrict__ beta) {
    __shared__ float s_sum[8], s_sq[8];
    const int row = blockIdx.x;
    const float4* xr = reinterpret_cast<const float4*>(x) + (size_t)row * (DD / 4);
    float4 v = xr[threadIdx.x];
    float s = v.x + v.y + v.z + v.w;
    float q = v.x * v.x + v.y * v.y + v.z * v.z + v.w * v.w;
    #pragma unroll
    for (int o = 16; o; o >>= 1) {
        s += __shfl_xor_sync(0xffffffffu, s, o);
        q += __shfl_xor_sync(0xffffffffu, q, o);
    }
    const int warp = threadIdx.x >> 5, lane = threadIdx.x & 31;
    if (lane == 0) { s_sum[warp] = s; s_sq[warp] = q; }
    __syncthreads();
    if (warp == 0) {
        s = (lane < 8) ? s_sum[lane] : 0.f;
        q = (lane < 8) ? s_sq[lane] : 0.f;
        #pragma unroll
        for (int o = 4; o; o >>= 1) {
            s += __shfl_xor_sync(0xffffffffu, s, o);
            q += __shfl_xor_sync(0xffffffffu, q, o);
        }
        if (lane == 0) { s_sum[0] = s; s_sq[0] = q; }
    }
    __syncthreads();
    const float mean = s_sum[0] * (1.f / DD);
    const float var  = s_sq[0] * (1.f / DD) - mean * mean;
    const float rstd = rsqrtf(var + 1e-5f);
    const float4 gg = reinterpret_cast<const float4*>(gamma)[threadIdx.x];
    const float4 bb = reinterpret_cast<const float4*>(beta)[threadIdx.x];
    float o0 = (v.x - mean) * rstd * gg.x + bb.x;
    float o1 = (v.y - mean) * rstd * gg.y + bb.y;
    float o2 = (v.z - mean) * rstd * gg.z + bb.z;
    float o3 = (v.w - mean) * rstd * gg.w + bb.w;
    __nv_bfloat16 h0, h1, h2, h3, l0, l1, l2, l3;
    split2(o0, h0, l0); split2(o1, h1, l1); split2(o2, h2, l2); split2(o3, h3, l3);
    __nv_bfloat16* dst = g_a2 + (size_t)row * KSP2 + threadIdx.x * 4;
    __nv_bfloat162 hA(h0, h1), hB(h2, h3), lA(l0, l1), lB(l2, l3);
    reinterpret_cast<__nv_bfloat162*>(dst)[0] = hA;
    reinterpret_cast<__nv_bfloat162*>(dst)[1] = hB;
    reinterpret_cast<__nv_bfloat162*>(dst + 1024)[0] = lA;
    reinterpret_cast<__nv_bfloat162*>(dst + 1024)[1] = lB;
}

// ---------------- generic fp32 -> [hi|lo] bf16 [rows,2048] ------------------
__global__ void split_kernel(const float* __restrict__ src, __nv_bfloat16* __restrict__ dst,
                             int rows) {
    int i = blockIdx.x * blockDim.x + threadIdx.x;
    if (i >= rows * 256) return;
    int row = i >> 8;
    int g = i & 255;
    float4 v = reinterpret_cast<const float4*>(src + (size_t)row * DD)[g];
    __nv_bfloat16 h0, h1, h2, h3, l0, l1, l2, l3;
    split2(v.x, h0, l0); split2(v.y, h1, l1); split2(v.z, h2, l2); split2(v.w, h3, l3);
    __nv_bfloat16* d = dst + (size_t)row * KSP2 + g * 4;
    __nv_bfloat162 hA(h0, h1), hB(h2, h3), lA(l0, l1), lB(l2, l3);
    reinterpret_cast<__nv_bfloat162*>(d)[0] = hA;
    reinterpret_cast<__nv_bfloat162*>(d)[1] = hB;
    reinterpret_cast<__nv_bfloat162*>(d + 1024)[0] = lA;
    reinterpret_cast<__nv_bfloat162*>(d + 1024)[1] = lB;
}

// ---------------- pack i/f weights -----------------------------------------
__global__ void combine_if_kernel(const float* __restrict__ iw,
                                  const float* __restrict__ ib,
                                  const float* __restrict__ fw,
                                  const float* __restrict__ fb) {
    int idx = blockIdx.x * blockDim.x + threadIdx.x;
    if (idx < 2 * HH * DD) {
        int nrow = idx / DD;
        g_wif[idx] = (nrow < HH) ? iw[idx] : fw[idx - HH * DD];
    }
    if (idx < 2 * HH) g_bif[idx] = (idx < HH) ? ib[idx] : fb[idx - HH];
}

// ---------------- cg2 tcgen05 GEMM: pair tile 256(M) x 512(N) ---------------
// out[m,n] = scale*(Ah·Bh + Ah·Bl + Al·Bh + bias) (+resid)
// cluster (2,1,1): rank r holds A rows [bm+r*128,128) and, for MMA half j,
// B rows [bn+j*256+r*128,128). D: each CTA's TMEM holds its 128 M-rows x 512 cols.
template <bool RESID>
__global__ void __launch_bounds__(256, 1) __cluster_dims__(2, 1, 1)
mma_gemm_cg2_kernel(
    const __nv_bfloat16* __restrict__ A2,
    const __nv_bfloat16* __restrict__ B2,
    const float* __restrict__ bias,
    const float* __restrict__ resid,
    float* __restrict__ out,
    int N, float scale)
{
#if HAS_TCGEN05
    extern __shared__ char smem_raw[];
    char* smem = (char*)(((uintptr_t)smem_raw + 1023) & ~(uintptr_t)1023);
    __shared__ __align__(16) uint64_t s_full[2];   // on rank0 (count=2)
    __shared__ __align__(16) uint64_t s_done[2];   // per-CTA (count=1, multicast)
    __shared__ uint32_t s_tmem;

    const int tid = threadIdx.x;
    const int wid = tid >> 5;
    const uint32_t rank = cluster_rank();
    const int bm = blockIdx.y * 256;
    const int bn = (blockIdx.x >> 1) * 512;
    const uint32_t smem_base = smem_u32(smem);
    const uint32_t full0 = smem_u32(&s_full[0]);
    const uint32_t full1 = smem_u32(&s_full[1]);
    const uint32_t done0 = smem_u32(&s_done[0]);
    const uint32_t done1 = smem_u32(&s_done[1]);

    if (wid == 0) TCGEN05_ALLOC_CG2(smem_u32(&s_tmem), 512);
    if (tid == 0) {
        if (rank == 0) { MBARRIER_INIT(full0, 2); MBARRIER_INIT(full1, 2); }
        MBARRIER_INIT(done0, 1);
        MBARRIER_INIT(done1, 1);
    }
    __syncthreads();
    const uint32_t tmem_d = s_tmem;
    CLUSTER_SYNC();   // mbar init visible cluster-wide before remote arrivals

    const char* Abase = (const char*)(A2 + (size_t)(bm + rank * 128) * KSP2);
    const char* Bj0   = (const char*)(B2 + (size_t)(bn + 0   + rank * 128) * KSP2);
    const char* Bj1   = (const char*)(B2 + (size_t)(bn + 256 + rank * 128) * KSP2);

    auto load_tile = [&](const char* src, char* dst) {
        #pragma unroll
        for (int i = 0; i < 4; ++i) {
            int cidx = tid + i * 256;
            int row = cidx >> 3;
            int c16 = cidx & 7;
            uint4 v = *(const uint4*)(src + (size_t)row * ROWB + c16 * 16);
            *(uint4*)(dst + SWZ128(row * 128 + c16 * 16)) = v;
        }
    };
    auto load_step = [&](int kc, int s) {
        char* sb = smem + s * STAGE;
        const size_t ko = (size_t)kc * 128;
        load_tile(Abase + ko,        sb);             // Ah (own 128 rows)
        load_tile(Abase + 2048 + ko, sb + 16384);     // Al
        load_tile(Bj0   + ko,        sb + 32768);     // B half0 hi
        load_tile(Bj0   + 2048 + ko, sb + 49152);     // B half0 lo
        load_tile(Bj1   + ko,        sb + 65536);     // B half1 hi
        load_tile(Bj1   + 2048 + ko, sb + 81920);     // B half1 lo
    };
    auto arrive_full = [&](int s) {
        // after __syncthreads: one thread fences generic->async and arrives on leader
        if (tid == 0) {
            FENCE_PROXY_ASYNC_ALL();
            if (rank == 0) MBARRIER_ARRIVE_LOCAL(s == 0 ? full0 : full1);
            else           MBARRIER_ARRIVE_CLUSTER(s == 0 ? full0 : full1, 0);
        }
    };

    load_step(0, 0);
    __syncthreads();
    arrive_full(0);

    int pf0 = 0, pf1 = 0;     // full phases (rank0 wid0)
    int pd0 = 0, pd1 = 0;     // done phases (all threads)
    for (int kc = 0; kc < NSTEP; ++kc) {
        const int s = kc & 1;
        if (rank == 0 && wid == 0) {
            if (elect_one_pred()) {
                if (s == 0) { MBARRIER_WAIT_PARITY(full0, pf0); pf0 ^= 1; }
                else        { MBARRIER_WAIT_PARITY(full1, pf1); pf1 ^= 1; }
                const uint32_t base = smem_base + s * STAGE;
                const uint64_t dAh = MAKE_SMEM_DESC(base);
                const uint64_t dAl = MAKE_SMEM_DESC(base + 16384);
                #pragma unroll
                for (int j = 0; j < 2; ++j) {
                    const uint64_t dBh = MAKE_SMEM_DESC(base + 32768 + j * 32768);
                    const uint64_t dBl = MAKE_SMEM_DESC(base + 49152 + j * 32768);
                    const uint32_t dt = tmem_d + j * 256;
                    #pragma unroll
                    for (int g = 0; g < 4; ++g)
                        TCGEN05_MMA_F16_SS_CG2(dt, dAh + g * 2, dBh + g * 2, MMA_IDESC2,
                                               (kc > 0) || (g > 0));
                    #pragma unroll
                    for (int g = 0; g < 4; ++g)
                        TCGEN05_MMA_F16_SS_CG2(dt, dAh + g * 2, dBl + g * 2, MMA_IDESC2, true);
                    #pragma unroll
                    for (int g = 0; g < 4; ++g)
                        TCGEN05_MMA_F16_SS_CG2(dt, dAl + g * 2, dBh + g * 2, MMA_IDESC2, true);
                }
                TCGEN05_COMMIT_MC_CG2(s == 0 ? done0 : done1, 0x3);
            }
        }
        if (kc + 1 < NSTEP) {
            const int s2 = (kc + 1) & 1;
            if (kc >= 1) {
                if (s2 == 0) { MBARRIER_WAIT_PARITY(done0, pd0); pd0 ^= 1; }
                else         { MBARRIER_WAIT_PARITY(done1, pd1); pd1 ^= 1; }
            }
            load_step(kc + 1, s2);
            __syncthreads();
            arrive_full(s2);
        }
    }
    // last step (kc=15) used buffer 1
    MBARRIER_WAIT_PARITY(done1, pd1);
    TCGEN05_FENCE_AFTER();

    // epilogue: 4 col-tiles of 128; warps 0-3 cols 0..63, 4-7 cols 64..127 per tile
    const int colbase = (wid >> 2) * 64;
    const int row = bm + (int)rank * 128 + (wid & 3) * 32 + (tid & 31);
    for (int t = 0; t < 4; ++t) {
        #pragma unroll
        for (int cb = 0; cb < 64; cb += 32) {
            uint32_t dr[32];
            TCGEN05_LD_X32(dr, tmem_d + t * 128 + colbase + cb);
            TCGEN05_WAIT_LD();
            TCGEN05_FENCE_BEFORE();
            #pragma unroll
            for (int c = 0; c < 32; c += 4) {
                const int col = bn + t * 128 + colbase + cb + c;
                float4 bs = *(const float4*)(bias + col);
                float4 o;
                o.x = scale * (__uint_as_float(dr[c + 0]) + bs.x);
                o.y = scale * (__uint_as_float(dr[c + 1]) + bs.y);
                o.z = scale * (__uint_as_float(dr[c + 2]) + bs.z);
                o.w = scale * (__uint_as_float(dr[c + 3]) + bs.w);
                if (RESID) {
                    float4 r = *(const float4*)(resid + (size_t)row * N + col);
                    o.x += r.x; o.y += r.y; o.z += r.z; o.w += r.w;
                }
                *(float4*)(out + (size_t)row * N + col) = o;
            }
        }
    }
    __syncthreads();
    if (tid == 0) {
        if (rank == 0) { mbar_inval(full0); mbar_inval(full1); }
        mbar_inval(done0); mbar_inval(done1);
    }
    __syncthreads();
    if (wid == 0) {
        TCGEN05_RELINQ_CG2();
        TCGEN05_DEALLOC_CG2(tmem_d, 512);
    }
    CLUSTER_SYNC();
#else
    // Fallback for the compute_103 PTX pass (never run on sm_103a HW).
    const int tid = threadIdx.x;
    const uint32_t rank = cluster_rank();
    const int bm = blockIdx.y * 256 + (int)rank * 128;
    const int bn = (blockIdx.x >> 1) * 512;
    const int r0 = (tid >> 4) * 8;
    const int c0 = (tid & 15) * 8;
    for (int t = 0; t < 4; ++t)
    for (int i = 0; i < 8; ++i) {
        const int row = bm + r0 + i;
        const __nv_bfloat16* ar = A2 + (size_t)row * KSP2;
        for (int j = 0; j < 8; ++j) {
            const int col = bn + t * 128 + c0 + j;
            const __nv_bfloat16* br = B2 + (size_t)col * KSP2;
            float acc = 0.f;
            for (int k = 0; k < 1024; ++k) {
                float ah = __bfloat162float(ar[k]), al = __bfloat162float(ar[1024 + k]);
                float bh = __bfloat162float(br[k]), bl = __bfloat162float(br[1024 + k]);
                acc += ah * bh + ah * bl + al * bh;
            }
            float o = scale * (acc + bias[col]);
            if (RESID) o += resid[(size_t)row * N + col];
            out[(size_t)row * N + col] = o;
        }
    }
#endif
}

// ---------------- cg1 GEMM (round-7 kernel, kept for the IF projection) -----
template <bool RESID>
__global__ void __launch_bounds__(256, 1) mma_gemm_kernel(
    const __nv_bfloat16* __restrict__ A2,
    const __nv_bfloat16* __restrict__ B2,
    const float* __restrict__ bias,
    const float* __restrict__ resid,
    float* __restrict__ out,
    int N, float scale, int ntiles)
{
#if HAS_TCGEN05
    extern __shared__ char smem_raw[];
    char* smem = (char*)(((uintptr_t)smem_raw + 1023) & ~(uintptr_t)1023);
    __shared__ __align__(16) uint64_t s_mbar[2];
    __shared__ uint32_t s_tmem;

    const int tid = threadIdx.x;
    const int wid = tid >> 5;
    const int bm = blockIdx.y * 128;
    const int bn = blockIdx.x * 256;
    const uint32_t smem_base = smem_u32(smem);

    if (wid == 0) {
        TCGEN05_ALLOC(smem_u32(&s_tmem), 256);
        TCGEN05_RELINQ();
    }
    if (tid == 0) {
        MBARRIER_INIT(smem_u32(&s_mbar[0]), 1);
        MBARRIER_INIT(smem_u32(&s_mbar[1]), 1);
    }
    __syncthreads();
    const uint32_t tmem_d = s_tmem;
    const uint32_t mbar0 = smem_u32(&s_mbar[0]);
    const uint32_t mbar1 = smem_u32(&s_mbar[1]);

    const char* Abase  = (const char*)(A2 + (size_t)bm * KSP2);
    const char* B0base = (const char*)(B2 + (size_t)bn * KSP2);
    const char* B1base = B0base + (size_t)128 * ROWB;

    auto load_tile = [&](const char* src, char* dst) {
        #pragma unroll
        for (int i = 0; i < 4; ++i) {
            int cidx = tid + i * 256;
            int row = cidx >> 3;
            int c16 = cidx & 7;
            uint4 v = *(const uint4*)(src + (size_t)row * ROWB + c16 * 16);
            *(uint4*)(dst + SWZ128(row * 128 + c16 * 16)) = v;
        }
    };
    auto load_step = [&](int kc, int s) {
        char* sb = smem + s * STAGE;
        const size_t ko = (size_t)kc * 128;
        load_tile(Abase  + ko,        sb);
        load_tile(Abase  + 2048 + ko, sb + 16384);
        load_tile(B0base + ko,        sb + 32768);
        load_tile(B0base + 2048 + ko, sb + 49152);
        if (ntiles == 2) {
            load_tile(B1base + ko,        sb + 65536);
            load_tile(B1base + 2048 + ko, sb + 81920);
        }
    };

    load_step(0, 0);
    __syncthreads();

    int phase0 = 0, phase1 = 0;
    for (int kc = 0; kc < NSTEP; ++kc) {
        const int s = kc & 1;
        if (wid == 0) {
            FENCE_PROXY_ASYNC();
            if (elect_one_pred()) {
                const uint32_t base = smem_base + s * STAGE;
                const uint64_t dAh = MAKE_SMEM_DESC(base);
                const uint64_t dAl = MAKE_SMEM_DESC(base + 16384);
                for (int t = 0; t < ntiles; ++t) {
                    const uint64_t dBh = MAKE_SMEM_DESC(base + 32768 + t * 32768);
                    const uint64_t dBl = MAKE_SMEM_DESC(base + 49152 + t * 32768);
                    const uint32_t dt = tmem_d + t * 128;
                    #pragma unroll
                    for (int j = 0; j < 4; ++j)
                        TCGEN05_MMA_F16_SS(dt, dAh + j * 2, dBh + j * 2, MMA_IDESC,
                                           (kc > 0) || (j > 0));
                    #pragma unroll
                    for (int j = 0; j < 4; ++j)
                        TCGEN05_MMA_F16_SS(dt, dAh + j * 2, dBl + j * 2, MMA_IDESC, true);
                    #pragma unroll
                    for (int j = 0; j < 4; ++j)
                        TCGEN05_MMA_F16_SS(dt, dAl + j * 2, dBh + j * 2, MMA_IDESC, true);
                }
                TCGEN05_COMMIT(s == 0 ? mbar0 : mbar1);
            }
        }
        if (kc + 1 < NSTEP) {
            const int s2 = (kc + 1) & 1;
            if (kc >= 1) {
                if (s2 == 0) { MBARRIER_WAIT_PARITY(mbar0, phase0); phase0 ^= 1; }
                else         { MBARRIER_WAIT_PARITY(mbar1, phase1); phase1 ^= 1; }
            }
            load_step(kc + 1, s2);
        }
        __syncthreads();
    }
    MBARRIER_WAIT_PARITY(mbar1, phase1);
    TCGEN05_FENCE_AFTER();

    const int colbase = (wid >> 2) * 64;
    const int row = bm + (wid & 3) * 32 + (tid & 31);
    for (int t = 0; t < ntiles; ++t) {
        #pragma unroll
        for (int cb = 0; cb < 64; cb += 32) {
            uint32_t dr[32];
            TCGEN05_LD_X32(dr, tmem_d + t * 128 + colbase + cb);
            TCGEN05_WAIT_LD();
            TCGEN05_FENCE_BEFORE();
            #pragma unroll
            for (int c = 0; c < 32; c += 4) {
                const int col = bn + t * 128 + colbase + cb + c;
                float4 bs = *(const float4*)(bias + col);
                float4 o;
                o.x = scale * (__uint_as_float(dr[c + 0]) + bs.x);
                o.y = scale * (__uint_as_float(dr[c + 1]) + bs.y);
                o.z = scale * (__uint_as_float(dr[c + 2]) + bs.z);
                o.w = scale * (__uint_as_float(dr[c + 3]) + bs.w);
                if (RESID) {
                    float4 r = *(const float4*)(resid + (size_t)row * N + col);
                    o.x += r.x; o.y += r.y; o.z += r.z; o.w += r.w;
                }
                *(float4*)(out + (size_t)row * N + col) = o;
            }
        }
    }
    __syncthreads();
    if (tid == 0) { mbar_inval(mbar0); mbar_inval(mbar1); }
    __syncthreads();
    if (wid == 0) TCGEN05_DEALLOC(tmem_d, 256);
#else
    const int tid = threadIdx.x;
    const int bm = blockIdx.y * 128;
    const int bn = blockIdx.x * 256;
    const int r0 = (tid >> 4) * 8;
    const int c0 = (tid & 15) * 8;
    for (int t = 0; t < ntiles; ++t)
    for (int i = 0; i < 8; ++i) {
        const int row = bm + r0 + i;
        const __nv_bfloat16* ar = A2 + (size_t)row * KSP2;
        for (int j = 0; j < 8; ++j) {
            const int col = bn + t * 128 + c0 + j;
            const __nv_bfloat16* br = B2 + (size_t)col * KSP2;
            float acc = 0.f;
            for (int k = 0; k < 1024; ++k) {
                float ah = __bfloat162float(ar[k]), al = __bfloat162float(ar[1024 + k]);
                float bh = __bfloat162float(br[k]), bl = __bfloat162float(br[1024 + k]);
                acc += ah * bh + ah * bl + al * bh;
            }
            float o = scale * (acc + bias[col]);
            if (RESID) o += resid[(size_t)row * N + col];
            out[(size_t)row * N + col] = o;
        }
    }
#endif
}

// ---------------- chunked scan (round-7 proven form) -------------------------
__global__ void __launch_bounds__(256) scan_phase1_kernel() {
    const int tid = threadIdx.x;
    const int gid = blockIdx.x * 16 + (tid >> 4);
    const int e = tid & 15;
    const int j = gid >> 9;
    const int c = gid & 511;
    const int b = c >> 6, h = c & 63;
    const int t0 = j * CHUNK;

    size_t off = ((size_t)b * LL + t0) * DD + h * HDIM + e;
    size_t offIF = ((size_t)b * LL + t0) * (2 * HH);

    float C[16];
    #pragma unroll
    for (int d = 0; d < 16; ++d) C[d] = 0.f;
    float n = 0.f, m = -1e30f, F = 0.f;

    for (int t = 0; t < CHUNK; ++t) {
        const float ke = g_k[off], ve = g_v[off];
        const float it = g_if[offIF + h];
        const float ft = g_if[offIF + HH + h];
        const float m_new = fmaxf(ft + m, it);
        const float fd = __expf(ft + m - m_new);
        const float id = __expf(it - m_new);
        m = m_new; F += ft;
        const float kid = id * ke;
        n = fd * n + kid;
        #pragma unroll
        for (int d = 0; d < 16; ++d) {
            const float vd = __shfl_sync(0xffffffffu, ve, d, 16);
            C[d] = fd * C[d] + vd * kid;
        }
        off += DD; offIF += 2 * HH;
    }
    float* cs = g_Cloc + (size_t)gid * 256;
    #pragma unroll
    for (int d = 0; d < 16; ++d) cs[d * 16 + e] = C[d];
    g_nloc[(size_t)gid * 16 + e] = n;
    if (e == 0) { g_mloc[gid] = m; g_Floc[gid] = F; }
}

__global__ void __launch_bounds__(256) scan_phase2_kernel() {
    const int tid = threadIdx.x;
    const int c = blockIdx.x * 16 + (tid >> 4);
    const int e = tid & 15;

    float C[16];
    #pragma unroll
    for (int d = 0; d < 16; ++d) C[d] = 0.f;
    float n = 0.f, m = 0.f;

    for (int j = 0; j < NCH; ++j) {
        const int sid = j * NCHAINS + c;
        float* ci = g_Cin + (size_t)sid * 256;
        #pragma unroll
        for (int d = 0; d < 16; ++d) ci[d * 16 + e] = C[d];
        g_nin[(size_t)sid * 16 + e] = n;
        if (e == 0) g_min[sid] = m;
        const float ml = g_mloc[sid];
        const float F  = g_Floc[sid];
        const float mo = fmaxf(m + F, ml);
        const float a  = __expf(m + F - mo);
        const float bb = __expf(ml - mo);
        const float* cl = g_Cloc + (size_t)sid * 256;
        #pragma unroll
        for (int d = 0; d < 16; ++d) C[d] = a * C[d] + bb * cl[d * 16 + e];
        n = a * n + bb * g_nloc[(size_t)sid * 16 + e];
        m = mo;
    }
}

__global__ void __launch_bounds__(256) scan_phase3_kernel() {
    const int tid = threadIdx.x;
    const int gid = blockIdx.x * 16 + (tid >> 4);
    const int e = tid & 15;
    const int j = gid >> 9;
    const int c = gid & 511;
    const int b = c >> 6, h = c & 63;
    const int t0 = j * CHUNK;

    size_t off = ((size_t)b * LL + t0) * DD + h * HDIM + e;
    size_t offIF = ((size_t)b * LL + t0) * (2 * HH);
    size_t h2off = ((size_t)b * LL + t0) * KSP2 + h * HDIM + e;

    const float* ci = g_Cin + (size_t)gid * 256;
    float C[16];
    #pragma unroll
    for (int d = 0; d < 16; ++d) C[d] = ci[d * 16 + e];
    float n = g_nin[(size_t)gid * 16 + e];
    float m = g_min[gid];

    for (int t = 0; t < CHUNK; ++t) {
        const float qe = g_q[off], ke = g_k[off], ve = g_v[off];
        const float it = g_if[offIF + h];
        const float ft = g_if[offIF + HH + h];
        const float m_new = fmaxf(ft + m, it);
        const float fd = __expf(ft + m - m_new);
        const float id = __expf(it - m_new);
        m = m_new;
        const float kid = id * ke;
        n = fd * n + kid;

        float cq = 0.f;
        #pragma unroll
        for (int d = 0; d < 16; ++d) {
            const float vd = __shfl_sync(0xffffffffu, ve, d, 16);
            const float qd = __shfl_sync(0xffffffffu, qe, d, 16);
            C[d] = fd * C[d] + vd * kid;
            cq = fmaf(C[d], qd, cq);
        }

        float nq = n * qe;
        #pragma unroll
        for (int o = 8; o; o >>= 1) nq += __shfl_xor_sync(0xffffffffu, nq, o, 16);
        const float denom = fmaxf(fabsf(nq), 1.0f);

        const float hval = cq / denom;
        __nv_bfloat16 hh, hl;
        split2(hval, hh, hl);
        g_h2[h2off] = hh;
        g_h2[h2off + 1024] = hl;

        off += DD; offIF += 2 * HH; h2off += KSP2;
    }
}

// ---------------- launch ----------------------------------------------------
extern "C" void kernel_launch(void* const* d_in, const int* in_sizes, int n_in,
                              void* d_out, int out_size) {
    (void)in_sizes; (void)n_in; (void)out_size;
    const float* x     = (const float*)d_in[0];
    const float* gamma = (const float*)d_in[1];
    const float* beta  = (const float*)d_in[2];
    const float* qw    = (const float*)d_in[3];
    const float* qb    = (const float*)d_in[4];
    const float* kw    = (const float*)d_in[5];
    const float* kb    = (const float*)d_in[6];
    const float* vw    = (const float*)d_in[7];
    const float* vb    = (const float*)d_in[8];
    const float* ow    = (const float*)d_in[9];
    const float* ob    = (const float*)d_in[10];
    const float* iw    = (const float*)d_in[11];
    const float* ib    = (const float*)d_in[12];
    const float* fw    = (const float*)d_in[13];
    const float* fb    = (const float*)d_in[14];
    float* out = (float*)d_out;

    __nv_bfloat16 *a2, *h2, *qw2, *kw2, *vw2, *ow2, *wif2;
    float *qp, *kp, *vp, *ifp, *wif, *bif;
    cudaGetSymbolAddress((void**)&a2,   g_a2);
    cudaGetSymbolAddress((void**)&h2,   g_h2);
    cudaGetSymbolAddress((void**)&qw2,  g_qw2);
    cudaGetSymbolAddress((void**)&kw2,  g_kw2);
    cudaGetSymbolAddress((void**)&vw2,  g_vw2);
    cudaGetSymbolAddress((void**)&ow2,  g_ow2);
    cudaGetSymbolAddress((void**)&wif2, g_wif2);
    cudaGetSymbolAddress((void**)&qp,   g_q);
    cudaGetSymbolAddress((void**)&kp,   g_k);
    cudaGetSymbolAddress((void**)&vp,   g_v);
    cudaGetSymbolAddress((void**)&ifp,  g_if);
    cudaGetSymbolAddress((void**)&wif,  g_wif);
    cudaGetSymbolAddress((void**)&bif,  g_bif);

    cudaFuncSetAttribute(mma_gemm_cg2_kernel<false>,
                         cudaFuncAttributeMaxDynamicSharedMemorySize, SMEM_SZ);
    cudaFuncSetAttribute(mma_gemm_cg2_kernel<true>,
                         cudaFuncAttributeMaxDynamicSharedMemorySize, SMEM_SZ);
    cudaFuncSetAttribute(mma_gemm_kernel<false>,
                         cudaFuncAttributeMaxDynamicSharedMemorySize, SMEM_SZ);

    dim3 gridCg2(2 * (DD / 512), MROWS / 256);   // (4, 128) -> 512 CTAs (256 pairs)
    dim3 gridIF(1, MROWS / 128);                 // (1, 256)

    // launch order arranged so the ncu capture (6th launch) hits the q GEMM
    ln_split_kernel<<<MROWS, 256>>>(x, gamma, beta);                          // 0
    combine_if_kernel<<<(2 * HH * DD + 255) / 256, 256>>>(iw, ib, fw, fb);    // 1
    split_kernel<<<(DD * 256 + 255) / 256, 256>>>(qw, qw2, DD);               // 2
    split_kernel<<<(DD * 256 + 255) / 256, 256>>>(kw, kw2, DD);               // 3
    split_kernel<<<(DD * 256 + 255) / 256, 256>>>(vw, vw2, DD);               // 4
    mma_gemm_cg2_kernel<false><<<gridCg2, 256, SMEM_SZ>>>(a2, qw2, qb, nullptr, qp, DD, 1.0f);   // 5 <- ncu
    split_kernel<<<(DD * 256 + 255) / 256, 256>>>(ow, ow2, DD);               // 6
    split_kernel<<<(2 * HH * 256 + 255) / 256, 256>>>(wif, wif2, 2 * HH);     // 7
    mma_gemm_cg2_kernel<false><<<gridCg2, 256, SMEM_SZ>>>(a2, kw2, kb, nullptr, kp, DD, 0.25f);
    mma_gemm_cg2_kernel<false><<<gridCg2, 256, SMEM_SZ>>>(a2, vw2, vb, nullptr, vp, DD, 1.0f);
    mma_gemm_kernel<false><<<gridIF, 256, SMEM_SZ>>>(a2, wif2, bif, nullptr, ifp, 2 * HH, 1.0f, 1);

    scan_phase1_kernel<<<NSUM / 16, 256>>>();
    scan_phase2_kernel<<<NCHAINS / 16, 256>>>();
    scan_phase3_kernel<<<NSUM / 16, 256>>>();

    mma_gemm_cg2_kernel<true><<<gridCg2, 256, SMEM_SZ>>>(h2, ow2, ob, x, out, DD, 1.0f);
}

// round 15
// speedup vs baseline: 1.7090x; 1.0276x over previous
#include <cuda_runtime.h>
#include <cuda_bf16.h>
#include <cstdint>
#include <math.h>

#define BB 8
#define LL 4096
#define DD 1024
#define HH 64
#define HDIM 16
#define MROWS (BB*LL)        // 32768
#define KSP2 2048            // [hi | lo] * 1024
#define ROWB 4096            // bytes per [hi|lo] row
#define NSTEP 16             // 1024/64 k-steps in GEMM

#define CHUNK 64
#define NCH (LL/CHUNK)       // 64 time-chunks
#define NCHAINS (BB*HH)      // 512
#define NSUM (NCH*NCHAINS)   // 32768

#define STAGE 98304          // 96KB per stage (6 x 16KB tiles)
#define SMEM_SZ (2*STAGE + 1024)

#if defined(__CUDA_ARCH__) && (__CUDA_ARCH__ == 1030) && defined(__CUDA_ARCH_FEAT_SM103_ALL)
#define HAS_TCGEN05 1
#else
#define HAS_TCGEN05 0
#endif

// ---------------- device scratch ------------------------------------------
__device__ __nv_bfloat16 g_a2[(size_t)MROWS * KSP2];   // split xn [hi|lo]
__device__ __nv_bfloat16 g_h2[(size_t)MROWS * KSP2];   // split hs [hi|lo]
__device__ float g_q [(size_t)MROWS * DD];
__device__ float g_k [(size_t)MROWS * DD];
__device__ float g_v [(size_t)MROWS * DD];
__device__ float g_if[(size_t)MROWS * 2 * HH];
__device__ __nv_bfloat16 g_qw2[(size_t)DD * KSP2];
__device__ __nv_bfloat16 g_kw2[(size_t)DD * KSP2];
__device__ __nv_bfloat16 g_vw2[(size_t)DD * KSP2];
__device__ __nv_bfloat16 g_ow2[(size_t)DD * KSP2];
__device__ __nv_bfloat16 g_wif2[(size_t)(2*HH) * KSP2];
__device__ float g_wif[2 * HH * DD];
__device__ float g_bif[2 * HH];
// chunked-scan summaries / entering states
__device__ float g_Cloc[(size_t)NSUM * 256];
__device__ float g_nloc[(size_t)NSUM * 16];
__device__ float g_mloc[NSUM];
__device__ float g_Floc[NSUM];
__device__ float g_Cin [(size_t)NSUM * 256];
__device__ float g_nin [(size_t)NSUM * 16];
__device__ float g_min [NSUM];

// ---------------- PTX helpers ------------------------------------------------
__device__ __forceinline__ uint32_t smem_u32(const void* p) {
    uint32_t a;
    asm("{ .reg .u64 t; cvta.to.shared.u64 t, %1; cvt.u32.u64 %0, t; }"
        : "=r"(a) : "l"(p));
    return a;
}
__device__ __forceinline__ uint32_t cluster_rank() {
    uint32_t r;
    asm("mov.u32 %0, %%cluster_ctarank;" : "=r"(r));
    return r;
}
#define CLUSTER_SYNC() do { \
    asm volatile("barrier.cluster.arrive.aligned;" ::: "memory"); \
    asm volatile("barrier.cluster.wait.aligned;" ::: "memory"); \
} while (0)

#if HAS_TCGEN05
__device__ __forceinline__ uint32_t elect_one_pred() {
    uint32_t pred;
    asm volatile("{\n\t.reg .pred p;\n\telect.sync _|p, 0xFFFFFFFF;\n\t"
                 "selp.b32 %0, 1, 0, p;\n\t}" : "=r"(pred));
    return pred;
}
#define TCGEN05_ALLOC(saddr, n) \
    asm volatile("tcgen05.alloc.cta_group::1.sync.aligned.shared::cta.b32 [%0], %1;" \
                 :: "r"((uint32_t)(saddr)), "r"((uint32_t)(n)) : "memory")
#define TCGEN05_DEALLOC(taddr, n) \
    asm volatile("tcgen05.dealloc.cta_group::1.sync.aligned.b32 %0, %1;" \
                 :: "r"(taddr), "r"((uint32_t)(n)))
#define TCGEN05_RELINQ() \
    asm volatile("tcgen05.relinquish_alloc_permit.cta_group::1.sync.aligned;")
#define TCGEN05_ALLOC_CG2(saddr, n) \
    asm volatile("tcgen05.alloc.cta_group::2.sync.aligned.shared::cta.b32 [%0], %1;" \
                 :: "r"((uint32_t)(saddr)), "r"((uint32_t)(n)) : "memory")
#define TCGEN05_DEALLOC_CG2(taddr, n) \
    asm volatile("tcgen05.dealloc.cta_group::2.sync.aligned.b32 %0, %1;" \
                 :: "r"(taddr), "r"((uint32_t)(n)))
#define TCGEN05_RELINQ_CG2() \
    asm volatile("tcgen05.relinquish_alloc_permit.cta_group::2.sync.aligned;")
#define TCGEN05_COMMIT(mbar) \
    asm volatile("tcgen05.commit.cta_group::1.mbarrier::arrive::one.shared::cluster.b64 [%0];" \
                 :: "r"((uint32_t)(mbar)) : "memory")
#define TCGEN05_COMMIT_MC_CG2(mbar, mask) \
    asm volatile("tcgen05.commit.cta_group::2.mbarrier::arrive::one.shared::cluster.multicast::cluster.b64 [%0], %1;" \
                 :: "r"((uint32_t)(mbar)), "h"((uint16_t)(mask)) : "memory")
#define TCGEN05_FENCE_AFTER() \
    asm volatile("tcgen05.fence::after_thread_sync;" ::: "memory")
#define TCGEN05_FENCE_BEFORE() \
    asm volatile("tcgen05.fence::before_thread_sync;" ::: "memory")
#define TCGEN05_WAIT_LD() \
    asm volatile("tcgen05.wait::ld.sync.aligned;" ::: "memory")
#define FENCE_PROXY_ASYNC() \
    asm volatile("fence.proxy.async.shared::cta;" ::: "memory")
#define FENCE_PROXY_ASYNC_ALL() \
    asm volatile("fence.proxy.async;" ::: "memory")
#define MBARRIER_INIT(mbar, cnt) \
    asm volatile("mbarrier.init.shared.b64 [%0], %1;" \
                 :: "r"((uint32_t)(mbar)), "r"((uint32_t)(cnt)) : "memory")
#define MBARRIER_ARRIVE_LOCAL(mbar) \
    asm volatile("mbarrier.arrive.shared.b64 _, [%0];" :: "r"((uint32_t)(mbar)) : "memory")
#define MBARRIER_ARRIVE_CLUSTER(addr, rankv) \
    asm volatile("{\n\t.reg .b32 ra;\n\tmapa.shared::cluster.u32 ra, %0, %1;\n\t" \
        "mbarrier.arrive.shared::cluster.b64 _, [ra];\n\t}" \
        :: "r"((uint32_t)(addr)), "r"((uint32_t)(rankv)) : "memory")
__device__ __forceinline__ void mbar_inval(uint32_t a) {
    asm volatile("mbarrier.inval.shared.b64 [%0];" :: "r"(a) : "memory");
}
#define MBARRIER_WAIT_PARITY(mbar, par) do { \
    uint32_t _m = (uint32_t)(mbar); uint32_t _p = (uint32_t)(par); uint32_t _d; \
    asm volatile("{\n\t.reg .pred p;\n\t" \
        "mbarrier.try_wait.parity.acquire.cta.shared::cta.b64 p, [%1], %2;\n\t" \
        "selp.b32 %0, 1, 0, p;\n\t}" : "=r"(_d) : "r"(_m), "r"(_p) : "memory"); \
    if (!_d) { \
        asm volatile("{\n\t.reg .pred P1;\n\t" \
            "WL_%=:\n\t" \
            "mbarrier.try_wait.parity.acquire.cta.shared::cta.b64 P1, [%0], %1, 0x989680;\n\t" \
            "@P1 bra.uni WD_%=;\n\tbra.uni WL_%=;\n\tWD_%=:\n\t}" \
            :: "r"(_m), "r"(_p) : "memory"); \
    } \
} while (0)
#define TCGEN05_MMA_F16_SS(dtm, adesc, bdesc, idesc, en) do { \
    uint32_t _e = (en) ? 1u : 0u; \
    asm volatile("{\n\t.reg .pred p;\n\tsetp.ne.u32 p, %5, 0;\n\t" \
        "tcgen05.mma.cta_group::1.kind::f16 [%0], %1, %2, %3, {%4, %4, %4, %4}, p;\n\t}" \
        :: "r"(dtm), "l"(adesc), "l"(bdesc), "r"(idesc), "r"(0u), "r"(_e) : "memory"); \
} while (0)
#define TCGEN05_MMA_F16_SS_CG2(dtm, adesc, bdesc, idesc, en) do { \
    uint32_t _e = (en) ? 1u : 0u; \
    asm volatile("{\n\t.reg .pred p;\n\tsetp.ne.u32 p, %5, 0;\n\t" \
        "tcgen05.mma.cta_group::2.kind::f16 [%0], %1, %2, %3, {%4,%4,%4,%4,%4,%4,%4,%4}, p;\n\t}" \
        :: "r"(dtm), "l"(adesc), "l"(bdesc), "r"(idesc), "r"(0u), "r"(_e) : "memory"); \
} while (0)
#define TCGEN05_LD_X32(r, taddr) \
    asm volatile("tcgen05.ld.sync.aligned.32x32b.x32.b32 " \
        "{%0, %1, %2, %3, %4, %5, %6, %7, %8, %9, %10, %11, %12, %13, %14, %15, " \
        "%16, %17, %18, %19, %20, %21, %22, %23, %24, %25, %26, %27, %28, %29, %30, %31}, [%32];" \
        : "=r"((r)[0]),  "=r"((r)[1]),  "=r"((r)[2]),  "=r"((r)[3]), \
          "=r"((r)[4]),  "=r"((r)[5]),  "=r"((r)[6]),  "=r"((r)[7]), \
          "=r"((r)[8]),  "=r"((r)[9]),  "=r"((r)[10]), "=r"((r)[11]), \
          "=r"((r)[12]), "=r"((r)[13]), "=r"((r)[14]), "=r"((r)[15]), \
          "=r"((r)[16]), "=r"((r)[17]), "=r"((r)[18]), "=r"((r)[19]), \
          "=r"((r)[20]), "=r"((r)[21]), "=r"((r)[22]), "=r"((r)[23]), \
          "=r"((r)[24]), "=r"((r)[25]), "=r"((r)[26]), "=r"((r)[27]), \
          "=r"((r)[28]), "=r"((r)[29]), "=r"((r)[30]), "=r"((r)[31]) \
        : "r"(taddr))

static constexpr uint64_t SMEM_DESC_BASE_SW128 =
    (uint64_t(2)  << 61) | (uint64_t(1) << 46) | (uint64_t(64) << 32) | (uint64_t(1) << 16);
#define MAKE_SMEM_DESC(a) (SMEM_DESC_BASE_SW128 | ((uint64_t)((a) >> 4) & 0x3FFF))

// idesc: f32 accum, bf16 A/B
static constexpr uint32_t MMA_IDESC =       // M=128, N=128 (cg1)
    (1u << 4) | (1u << 7) | (1u << 10) | ((128u / 8) << 17) | ((128u / 16) << 24);
static constexpr uint32_t MMA_IDESC2 =      // M=256, N=256 (cg2)
    (1u << 4) | (1u << 7) | (1u << 10) | ((256u / 8) << 17) | ((256u / 16) << 24);
#endif  // HAS_TCGEN05

#define SWZ128(off) ((off) ^ (((off) >> 3) & 0x70))

// ---------------- bf16 split helper ----------------------------------------
__device__ __forceinline__ void split2(float v, __nv_bfloat16& hi, __nv_bfloat16& lo) {
    hi = __float2bfloat16(v);
    lo = __float2bfloat16(v - __bfloat162float(hi));
}

// ---------------- LayerNorm fused with [hi|lo] bf16 output ------------------
__global__ void ln_split_kernel(const float* __restrict__ x,
                                const float* __restrict__ gamma,
                                const float* __restrict__ beta) {
    __shared__ float s_sum[8], s_sq[8];
    const int row = blockIdx.x;
    const float4* xr = reinterpret_cast<const float4*>(x) + (size_t)row * (DD / 4);
    float4 v = xr[threadIdx.x];
    float s = v.x + v.y + v.z + v.w;
    float q = v.x * v.x + v.y * v.y + v.z * v.z + v.w * v.w;
    #pragma unroll
    for (int o = 16; o; o >>= 1) {
        s += __shfl_xor_sync(0xffffffffu, s, o);
        q += __shfl_xor_sync(0xffffffffu, q, o);
    }
    const int warp = threadIdx.x >> 5, lane = threadIdx.x & 31;
    if (lane == 0) { s_sum[warp] = s; s_sq[warp] = q; }
    __syncthreads();
    if (warp == 0) {
        s = (lane < 8) ? s_sum[lane] : 0.f;
        q = (lane < 8) ? s_sq[lane] : 0.f;
        #pragma unroll
        for (int o = 4; o; o >>= 1) {
            s += __shfl_xor_sync(0xffffffffu, s, o);
            q += __shfl_xor_sync(0xffffffffu, q, o);
        }
        if (lane == 0) { s_sum[0] = s; s_sq[0] = q; }
    }
    __syncthreads();
    const float mean = s_sum[0] * (1.f / DD);
    const float var  = s_sq[0] * (1.f / DD) - mean * mean;
    const float rstd = rsqrtf(var + 1e-5f);
    const float4 gg = reinterpret_cast<const float4*>(gamma)[threadIdx.x];
    const float4 bb = reinterpret_cast<const float4*>(beta)[threadIdx.x];
    float o0 = (v.x - mean) * rstd * gg.x + bb.x;
    float o1 = (v.y - mean) * rstd * gg.y + bb.y;
    float o2 = (v.z - mean) * rstd * gg.z + bb.z;
    float o3 = (v.w - mean) * rstd * gg.w + bb.w;
    __nv_bfloat16 h0, h1, h2, h3, l0, l1, l2, l3;
    split2(o0, h0, l0); split2(o1, h1, l1); split2(o2, h2, l2); split2(o3, h3, l3);
    __nv_bfloat16* dst = g_a2 + (size_t)row * KSP2 + threadIdx.x * 4;
    __nv_bfloat162 hA(h0, h1), hB(h2, h3), lA(l0, l1), lB(l2, l3);
    reinterpret_cast<__nv_bfloat162*>(dst)[0] = hA;
    reinterpret_cast<__nv_bfloat162*>(dst)[1] = hB;
    reinterpret_cast<__nv_bfloat162*>(dst + 1024)[0] = lA;
    reinterpret_cast<__nv_bfloat162*>(dst + 1024)[1] = lB;
}

// ---------------- generic fp32 -> [hi|lo] bf16 [rows,2048] ------------------
__global__ void split_kernel(const float* __restrict__ src, __nv_bfloat16* __restrict__ dst,
                             int rows) {
    int i = blockIdx.x * blockDim.x + threadIdx.x;
    if (i >= rows * 256) return;
    int row = i >> 8;
    int g = i & 255;
    float4 v = reinterpret_cast<const float4*>(src + (size_t)row * DD)[g];
    __nv_bfloat16 h0, h1, h2, h3, l0, l1, l2, l3;
    split2(v.x, h0, l0); split2(v.y, h1, l1); split2(v.z, h2, l2); split2(v.w, h3, l3);
    __nv_bfloat16* d = dst + (size_t)row * KSP2 + g * 4;
    __nv_bfloat162 hA(h0, h1), hB(h2, h3), lA(l0, l1), lB(l2, l3);
    reinterpret_cast<__nv_bfloat162*>(d)[0] = hA;
    reinterpret_cast<__nv_bfloat162*>(d)[1] = hB;
    reinterpret_cast<__nv_bfloat162*>(d + 1024)[0] = lA;
    reinterpret_cast<__nv_bfloat162*>(d + 1024)[1] = lB;
}

// ---------------- pack i/f weights -----------------------------------------
__global__ void combine_if_kernel(const float* __restrict__ iw,
                                  const float* __restrict__ ib,
                                  const float* __restrict__ fw,
                                  const float* __restrict__ fb) {
    int idx = blockIdx.x * blockDim.x + threadIdx.x;
    if (idx < 2 * HH * DD) {
        int nrow = idx / DD;
        g_wif[idx] = (nrow < HH) ? iw[idx] : fw[idx - HH * DD];
    }
    if (idx < 2 * HH) g_bif[idx] = (idx < HH) ? ib[idx] : fb[idx - HH];
}

// ---------------- merged q/k/v cg2 GEMM: pairIdx selects matrix -------------
// grid (12, 128), cluster (2,1,1): pairIdx = blockIdx.x>>1; m = pairIdx%3
// (0=q,1=k,2=v); ngrp = pairIdx/3; bn = ngrp*512; bm = blockIdx.y*256.
__global__ void __launch_bounds__(256, 1) __cluster_dims__(2, 1, 1)
mma_gemm_qkv_kernel(
    const __nv_bfloat16* __restrict__ A2,
    const __nv_bfloat16* __restrict__ qw2, const __nv_bfloat16* __restrict__ kw2,
    const __nv_bfloat16* __restrict__ vw2,
    const float* __restrict__ qb, const float* __restrict__ kb,
    const float* __restrict__ vb,
    float* __restrict__ qo, float* __restrict__ ko, float* __restrict__ vo)
{
    const int pairIdx = blockIdx.x >> 1;
    const int mm = pairIdx % 3;
    const int bn = (pairIdx / 3) * 512;
    const __nv_bfloat16* B2 = (mm == 0) ? qw2 : (mm == 1) ? kw2 : vw2;
    const float* bias = (mm == 0) ? qb : (mm == 1) ? kb : vb;
    float* out = (mm == 0) ? qo : (mm == 1) ? ko : vo;
    const float scale = (mm == 1) ? 0.25f : 1.0f;

#if HAS_TCGEN05
    extern __shared__ char smem_raw[];
    char* smem = (char*)(((uintptr_t)smem_raw + 1023) & ~(uintptr_t)1023);
    __shared__ __align__(16) uint64_t s_full[2];
    __shared__ __align__(16) uint64_t s_done[2];
    __shared__ uint32_t s_tmem;

    const int tid = threadIdx.x;
    const int wid = tid >> 5;
    const uint32_t rank = cluster_rank();
    const int bm = blockIdx.y * 256;
    const uint32_t smem_base = smem_u32(smem);
    const uint32_t full0 = smem_u32(&s_full[0]);
    const uint32_t full1 = smem_u32(&s_full[1]);
    const uint32_t done0 = smem_u32(&s_done[0]);
    const uint32_t done1 = smem_u32(&s_done[1]);

    if (wid == 0) TCGEN05_ALLOC_CG2(smem_u32(&s_tmem), 512);
    if (tid == 0) {
        if (rank == 0) { MBARRIER_INIT(full0, 2); MBARRIER_INIT(full1, 2); }
        MBARRIER_INIT(done0, 1);
        MBARRIER_INIT(done1, 1);
    }
    __syncthreads();
    const uint32_t tmem_d = s_tmem;
    CLUSTER_SYNC();

    const char* Abase = (const char*)(A2 + (size_t)(bm + rank * 128) * KSP2);
    const char* Bj0   = (const char*)(B2 + (size_t)(bn + 0   + rank * 128) * KSP2);
    const char* Bj1   = (const char*)(B2 + (size_t)(bn + 256 + rank * 128) * KSP2);

    auto load_tile = [&](const char* src, char* dst) {
        #pragma unroll
        for (int i = 0; i < 4; ++i) {
            int cidx = tid + i * 256;
            int row = cidx >> 3;
            int c16 = cidx & 7;
            uint4 v = *(const uint4*)(src + (size_t)row * ROWB + c16 * 16);
            *(uint4*)(dst + SWZ128(row * 128 + c16 * 16)) = v;
        }
    };
    auto load_step = [&](int kc, int s) {
        char* sb = smem + s * STAGE;
        const size_t ko = (size_t)kc * 128;
        load_tile(Abase + ko,        sb);
        load_tile(Abase + 2048 + ko, sb + 16384);
        load_tile(Bj0   + ko,        sb + 32768);
        load_tile(Bj0   + 2048 + ko, sb + 49152);
        load_tile(Bj1   + ko,        sb + 65536);
        load_tile(Bj1   + 2048 + ko, sb + 81920);
    };
    auto arrive_full = [&](int s) {
        if (tid == 0) {
            FENCE_PROXY_ASYNC_ALL();
            if (rank == 0) MBARRIER_ARRIVE_LOCAL(s == 0 ? full0 : full1);
            else           MBARRIER_ARRIVE_CLUSTER(s == 0 ? full0 : full1, 0);
        }
    };

    load_step(0, 0);
    __syncthreads();
    arrive_full(0);

    int pf0 = 0, pf1 = 0;
    int pd0 = 0, pd1 = 0;
    for (int kc = 0; kc < NSTEP; ++kc) {
        const int s = kc & 1;
        if (rank == 0 && wid == 0) {
            if (elect_one_pred()) {
                if (s == 0) { MBARRIER_WAIT_PARITY(full0, pf0); pf0 ^= 1; }
                else        { MBARRIER_WAIT_PARITY(full1, pf1); pf1 ^= 1; }
                const uint32_t base = smem_base + s * STAGE;
                const uint64_t dAh = MAKE_SMEM_DESC(base);
                const uint64_t dAl = MAKE_SMEM_DESC(base + 16384);
                #pragma unroll
                for (int j = 0; j < 2; ++j) {
                    const uint64_t dBh = MAKE_SMEM_DESC(base + 32768 + j * 32768);
                    const uint64_t dBl = MAKE_SMEM_DESC(base + 49152 + j * 32768);
                    const uint32_t dt = tmem_d + j * 256;
                    #pragma unroll
                    for (int g = 0; g < 4; ++g)
                        TCGEN05_MMA_F16_SS_CG2(dt, dAh + g * 2, dBh + g * 2, MMA_IDESC2,
                                               (kc > 0) || (g > 0));
                    #pragma unroll
                    for (int g = 0; g < 4; ++g)
                        TCGEN05_MMA_F16_SS_CG2(dt, dAh + g * 2, dBl + g * 2, MMA_IDESC2, true);
                    #pragma unroll
                    for (int g = 0; g < 4; ++g)
                        TCGEN05_MMA_F16_SS_CG2(dt, dAl + g * 2, dBh + g * 2, MMA_IDESC2, true);
                }
                TCGEN05_COMMIT_MC_CG2(s == 0 ? done0 : done1, 0x3);
            }
        }
        if (kc + 1 < NSTEP) {
            const int s2 = (kc + 1) & 1;
            if (kc >= 1) {
                if (s2 == 0) { MBARRIER_WAIT_PARITY(done0, pd0); pd0 ^= 1; }
                else         { MBARRIER_WAIT_PARITY(done1, pd1); pd1 ^= 1; }
            }
            load_step(kc + 1, s2);
            __syncthreads();
            arrive_full(s2);
        }
    }
    MBARRIER_WAIT_PARITY(done1, pd1);
    TCGEN05_FENCE_AFTER();

    const int colbase = (wid >> 2) * 64;
    const int row = bm + (int)rank * 128 + (wid & 3) * 32 + (tid & 31);
    for (int t = 0; t < 4; ++t) {
        #pragma unroll
        for (int cb = 0; cb < 64; cb += 32) {
            uint32_t dr[32];
            TCGEN05_LD_X32(dr, tmem_d + t * 128 + colbase + cb);
            TCGEN05_WAIT_LD();
            TCGEN05_FENCE_BEFORE();
            #pragma unroll
            for (int c = 0; c < 32; c += 4) {
                const int col = bn + t * 128 + colbase + cb + c;
                float4 bs = *(const float4*)(bias + col);
                float4 o;
                o.x = scale * (__uint_as_float(dr[c + 0]) + bs.x);
                o.y = scale * (__uint_as_float(dr[c + 1]) + bs.y);
                o.z = scale * (__uint_as_float(dr[c + 2]) + bs.z);
                o.w = scale * (__uint_as_float(dr[c + 3]) + bs.w);
                *(float4*)(out + (size_t)row * DD + col) = o;
            }
        }
    }
    __syncthreads();
    if (tid == 0) {
        if (rank == 0) { mbar_inval(full0); mbar_inval(full1); }
        mbar_inval(done0); mbar_inval(done1);
    }
    __syncthreads();
    if (wid == 0) {
        TCGEN05_RELINQ_CG2();
        TCGEN05_DEALLOC_CG2(tmem_d, 512);
    }
    CLUSTER_SYNC();
#else
    const int tid = threadIdx.x;
    const uint32_t rank = cluster_rank();
    const int bm = blockIdx.y * 256 + (int)rank * 128;
    const int r0 = (tid >> 4) * 8;
    const int c0 = (tid & 15) * 8;
    for (int t = 0; t < 4; ++t)
    for (int i = 0; i < 8; ++i) {
        const int row = bm + r0 + i;
        const __nv_bfloat16* ar = A2 + (size_t)row * KSP2;
        for (int j = 0; j < 8; ++j) {
            const int col = bn + t * 128 + c0 + j;
            const __nv_bfloat16* br = B2 + (size_t)col * KSP2;
            float acc = 0.f;
            for (int k = 0; k < 1024; ++k) {
                float ah = __bfloat162float(ar[k]), al = __bfloat162float(ar[1024 + k]);
                float bh = __bfloat162float(br[k]), bl = __bfloat162float(br[1024 + k]);
                acc += ah * bh + ah * bl + al * bh;
            }
            out[(size_t)row * DD + col] = scale * (acc + bias[col]);
        }
    }
#endif
}

// ---------------- cg2 GEMM (O projection with residual) ---------------------
template <bool RESID>
__global__ void __launch_bounds__(256, 1) __cluster_dims__(2, 1, 1)
mma_gemm_cg2_kernel(
    const __nv_bfloat16* __restrict__ A2,
    const __nv_bfloat16* __restrict__ B2,
    const float* __restrict__ bias,
    const float* __restrict__ resid,
    float* __restrict__ out,
    int N, float scale)
{
#if HAS_TCGEN05
    extern __shared__ char smem_raw[];
    char* smem = (char*)(((uintptr_t)smem_raw + 1023) & ~(uintptr_t)1023);
    __shared__ __align__(16) uint64_t s_full[2];
    __shared__ __align__(16) uint64_t s_done[2];
    __shared__ uint32_t s_tmem;

    const int tid = threadIdx.x;
    const int wid = tid >> 5;
    const uint32_t rank = cluster_rank();
    const int bm = blockIdx.y * 256;
    const int bn = (blockIdx.x >> 1) * 512;
    const uint32_t smem_base = smem_u32(smem);
    const uint32_t full0 = smem_u32(&s_full[0]);
    const uint32_t full1 = smem_u32(&s_full[1]);
    const uint32_t done0 = smem_u32(&s_done[0]);
    const uint32_t done1 = smem_u32(&s_done[1]);

    if (wid == 0) TCGEN05_ALLOC_CG2(smem_u32(&s_tmem), 512);
    if (tid == 0) {
        if (rank == 0) { MBARRIER_INIT(full0, 2); MBARRIER_INIT(full1, 2); }
        MBARRIER_INIT(done0, 1);
        MBARRIER_INIT(done1, 1);
    }
    __syncthreads();
    const uint32_t tmem_d = s_tmem;
    CLUSTER_SYNC();

    const char* Abase = (const char*)(A2 + (size_t)(bm + rank * 128) * KSP2);
    const char* Bj0   = (const char*)(B2 + (size_t)(bn + 0   + rank * 128) * KSP2);
    const char* Bj1   = (const char*)(B2 + (size_t)(bn + 256 + rank * 128) * KSP2);

    auto load_tile = [&](const char* src, char* dst) {
        #pragma unroll
        for (int i = 0; i < 4; ++i) {
            int cidx = tid + i * 256;
            int row = cidx >> 3;
            int c16 = cidx & 7;
            uint4 v = *(const uint4*)(src + (size_t)row * ROWB + c16 * 16);
            *(uint4*)(dst + SWZ128(row * 128 + c16 * 16)) = v;
        }
    };
    auto load_step = [&](int kc, int s) {
        char* sb = smem + s * STAGE;
        const size_t ko = (size_t)kc * 128;
        load_tile(Abase + ko,        sb);
        load_tile(Abase + 2048 + ko, sb + 16384);
        load_tile(Bj0   + ko,        sb + 32768);
        load_tile(Bj0   + 2048 + ko, sb + 49152);
        load_tile(Bj1   + ko,        sb + 65536);
        load_tile(Bj1   + 2048 + ko, sb + 81920);
    };
    auto arrive_full = [&](int s) {
        if (tid == 0) {
            FENCE_PROXY_ASYNC_ALL();
            if (rank == 0) MBARRIER_ARRIVE_LOCAL(s == 0 ? full0 : full1);
            else           MBARRIER_ARRIVE_CLUSTER(s == 0 ? full0 : full1, 0);
        }
    };

    load_step(0, 0);
    __syncthreads();
    arrive_full(0);

    int pf0 = 0, pf1 = 0;
    int pd0 = 0, pd1 = 0;
    for (int kc = 0; kc < NSTEP; ++kc) {
        const int s = kc & 1;
        if (rank == 0 && wid == 0) {
            if (elect_one_pred()) {
                if (s == 0) { MBARRIER_WAIT_PARITY(full0, pf0); pf0 ^= 1; }
                else        { MBARRIER_WAIT_PARITY(full1, pf1); pf1 ^= 1; }
                const uint32_t base = smem_base + s * STAGE;
                const uint64_t dAh = MAKE_SMEM_DESC(base);
                const uint64_t dAl = MAKE_SMEM_DESC(base + 16384);
                #pragma unroll
                for (int j = 0; j < 2; ++j) {
                    const uint64_t dBh = MAKE_SMEM_DESC(base + 32768 + j * 32768);
                    const uint64_t dBl = MAKE_SMEM_DESC(base + 49152 + j * 32768);
                    const uint32_t dt = tmem_d + j * 256;
                    #pragma unroll
                    for (int g = 0; g < 4; ++g)
                        TCGEN05_MMA_F16_SS_CG2(dt, dAh + g * 2, dBh + g * 2, MMA_IDESC2,
                                               (kc > 0) || (g > 0));
                    #pragma unroll
                    for (int g = 0; g < 4; ++g)
                        TCGEN05_MMA_F16_SS_CG2(dt, dAh + g * 2, dBl + g * 2, MMA_IDESC2, true);
                    #pragma unroll
                    for (int g = 0; g < 4; ++g)
                        TCGEN05_MMA_F16_SS_CG2(dt, dAl + g * 2, dBh + g * 2, MMA_IDESC2, true);
                }
                TCGEN05_COMMIT_MC_CG2(s == 0 ? done0 : done1, 0x3);
            }
        }
        if (kc + 1 < NSTEP) {
            const int s2 = (kc + 1) & 1;
            if (kc >= 1) {
                if (s2 == 0) { MBARRIER_WAIT_PARITY(done0, pd0); pd0 ^= 1; }
                else         { MBARRIER_WAIT_PARITY(done1, pd1); pd1 ^= 1; }
            }
            load_step(kc + 1, s2);
            __syncthreads();
            arrive_full(s2);
        }
    }
    MBARRIER_WAIT_PARITY(done1, pd1);
    TCGEN05_FENCE_AFTER();

    const int colbase = (wid >> 2) * 64;
    const int row = bm + (int)rank * 128 + (wid & 3) * 32 + (tid & 31);
    for (int t = 0; t < 4; ++t) {
        #pragma unroll
        for (int cb = 0; cb < 64; cb += 32) {
            uint32_t dr[32];
            TCGEN05_LD_X32(dr, tmem_d + t * 128 + colbase + cb);
            TCGEN05_WAIT_LD();
            TCGEN05_FENCE_BEFORE();
            #pragma unroll
            for (int c = 0; c < 32; c += 4) {
                const int col = bn + t * 128 + colbase + cb + c;
                float4 bs = *(const float4*)(bias + col);
                float4 o;
                o.x = scale * (__uint_as_float(dr[c + 0]) + bs.x);
                o.y = scale * (__uint_as_float(dr[c + 1]) + bs.y);
                o.z = scale * (__uint_as_float(dr[c + 2]) + bs.z);
                o.w = scale * (__uint_as_float(dr[c + 3]) + bs.w);
                if (RESID) {
                    float4 r = *(const float4*)(resid + (size_t)row * N + col);
                    o.x += r.x; o.y += r.y; o.z += r.z; o.w += r.w;
                }
                *(float4*)(out + (size_t)row * N + col) = o;
            }
        }
    }
    __syncthreads();
    if (tid == 0) {
        if (rank == 0) { mbar_inval(full0); mbar_inval(full1); }
        mbar_inval(done0); mbar_inval(done1);
    }
    __syncthreads();
    if (wid == 0) {
        TCGEN05_RELINQ_CG2();
        TCGEN05_DEALLOC_CG2(tmem_d, 512);
    }
    CLUSTER_SYNC();
#else
    const int tid = threadIdx.x;
    const uint32_t rank = cluster_rank();
    const int bm = blockIdx.y * 256 + (int)rank * 128;
    const int bn = (blockIdx.x >> 1) * 512;
    const int r0 = (tid >> 4) * 8;
    const int c0 = (tid & 15) * 8;
    for (int t = 0; t < 4; ++t)
    for (int i = 0; i < 8; ++i) {
        const int row = bm + r0 + i;
        const __nv_bfloat16* ar = A2 + (size_t)row * KSP2;
        for (int j = 0; j < 8; ++j) {
            const int col = bn + t * 128 + c0 + j;
            const __nv_bfloat16* br = B2 + (size_t)col * KSP2;
            float acc = 0.f;
            for (int k = 0; k < 1024; ++k) {
                float ah = __bfloat162float(ar[k]), al = __bfloat162float(ar[1024 + k]);
                float bh = __bfloat162float(br[k]), bl = __bfloat162float(br[1024 + k]);
                acc += ah * bh + ah * bl + al * bh;
            }
            float o = scale * (acc + bias[col]);
            if (RESID) o += resid[(size_t)row * N + col];
            out[(size_t)row * N + col] = o;
        }
    }
#endif
}

// ---------------- cg1 GEMM (IF projection) ----------------------------------
template <bool RESID>
__global__ void __launch_bounds__(256, 1) mma_gemm_kernel(
    const __nv_bfloat16* __restrict__ A2,
    const __nv_bfloat16* __restrict__ B2,
    const float* __restrict__ bias,
    const float* __restrict__ resid,
    float* __restrict__ out,
    int N, float scale, int ntiles)
{
#if HAS_TCGEN05
    extern __shared__ char smem_raw[];
    char* smem = (char*)(((uintptr_t)smem_raw + 1023) & ~(uintptr_t)1023);
    __shared__ __align__(16) uint64_t s_mbar[2];
    __shared__ uint32_t s_tmem;

    const int tid = threadIdx.x;
    const int wid = tid >> 5;
    const int bm = blockIdx.y * 128;
    const int bn = blockIdx.x * 256;
    const uint32_t smem_base = smem_u32(smem);

    if (wid == 0) {
        TCGEN05_ALLOC(smem_u32(&s_tmem), 256);
        TCGEN05_RELINQ();
    }
    if (tid == 0) {
        MBARRIER_INIT(smem_u32(&s_mbar[0]), 1);
        MBARRIER_INIT(smem_u32(&s_mbar[1]), 1);
    }
    __syncthreads();
    const uint32_t tmem_d = s_tmem;
    const uint32_t mbar0 = smem_u32(&s_mbar[0]);
    const uint32_t mbar1 = smem_u32(&s_mbar[1]);

    const char* Abase  = (const char*)(A2 + (size_t)bm * KSP2);
    const char* B0base = (const char*)(B2 + (size_t)bn * KSP2);
    const char* B1base = B0base + (size_t)128 * ROWB;

    auto load_tile = [&](const char* src, char* dst) {
        #pragma unroll
        for (int i = 0; i < 4; ++i) {
            int cidx = tid + i * 256;
            int row = cidx >> 3;
            int c16 = cidx & 7;
            uint4 v = *(const uint4*)(src + (size_t)row * ROWB + c16 * 16);
            *(uint4*)(dst + SWZ128(row * 128 + c16 * 16)) = v;
        }
    };
    auto load_step = [&](int kc, int s) {
        char* sb = smem + s * STAGE;
        const size_t ko = (size_t)kc * 128;
        load_tile(Abase  + ko,        sb);
        load_tile(Abase  + 2048 + ko, sb + 16384);
        load_tile(B0base + ko,        sb + 32768);
        load_tile(B0base + 2048 + ko, sb + 49152);
        if (ntiles == 2) {
            load_tile(B1base + ko,        sb + 65536);
            load_tile(B1base + 2048 + ko, sb + 81920);
        }
    };

    load_step(0, 0);
    __syncthreads();

    int phase0 = 0, phase1 = 0;
    for (int kc = 0; kc < NSTEP; ++kc) {
        const int s = kc & 1;
        if (wid == 0) {
            FENCE_PROXY_ASYNC();
            if (elect_one_pred()) {
                const uint32_t base = smem_base + s * STAGE;
                const uint64_t dAh = MAKE_SMEM_DESC(base);
                const uint64_t dAl = MAKE_SMEM_DESC(base + 16384);
                for (int t = 0; t < ntiles; ++t) {
                    const uint64_t dBh = MAKE_SMEM_DESC(base + 32768 + t * 32768);
                    const uint64_t dBl = MAKE_SMEM_DESC(base + 49152 + t * 32768);
                    const uint32_t dt = tmem_d + t * 128;
                    #pragma unroll
                    for (int j = 0; j < 4; ++j)
                        TCGEN05_MMA_F16_SS(dt, dAh + j * 2, dBh + j * 2, MMA_IDESC,
                                           (kc > 0) || (j > 0));
                    #pragma unroll
                    for (int j = 0; j < 4; ++j)
                        TCGEN05_MMA_F16_SS(dt, dAh + j * 2, dBl + j * 2, MMA_IDESC, true);
                    #pragma unroll
                    for (int j = 0; j < 4; ++j)
                        TCGEN05_MMA_F16_SS(dt, dAl + j * 2, dBh + j * 2, MMA_IDESC, true);
                }
                TCGEN05_COMMIT(s == 0 ? mbar0 : mbar1);
            }
        }
        if (kc + 1 < NSTEP) {
            const int s2 = (kc + 1) & 1;
            if (kc >= 1) {
                if (s2 == 0) { MBARRIER_WAIT_PARITY(mbar0, phase0); phase0 ^= 1; }
                else         { MBARRIER_WAIT_PARITY(mbar1, phase1); phase1 ^= 1; }
            }
            load_step(kc + 1, s2);
        }
        __syncthreads();
    }
    MBARRIER_WAIT_PARITY(mbar1, phase1);
    TCGEN05_FENCE_AFTER();

    const int colbase = (wid >> 2) * 64;
    const int row = bm + (wid & 3) * 32 + (tid & 31);
    for (int t = 0; t < ntiles; ++t) {
        #pragma unroll
        for (int cb = 0; cb < 64; cb += 32) {
            uint32_t dr[32];
            TCGEN05_LD_X32(dr, tmem_d + t * 128 + colbase + cb);
            TCGEN05_WAIT_LD();
            TCGEN05_FENCE_BEFORE();
            #pragma unroll
            for (int c = 0; c < 32; c += 4) {
                const int col = bn + t * 128 + colbase + cb + c;
                float4 bs = *(const float4*)(bias + col);
                float4 o;
                o.x = scale * (__uint_as_float(dr[c + 0]) + bs.x);
                o.y = scale * (__uint_as_float(dr[c + 1]) + bs.y);
                o.z = scale * (__uint_as_float(dr[c + 2]) + bs.z);
                o.w = scale * (__uint_as_float(dr[c + 3]) + bs.w);
                if (RESID) {
                    float4 r = *(const float4*)(resid + (size_t)row * N + col);
                    o.x += r.x; o.y += r.y; o.z += r.z; o.w += r.w;
                }
                *(float4*)(out + (size_t)row * N + col) = o;
            }
        }
    }
    __syncthreads();
    if (tid == 0) { mbar_inval(mbar0); mbar_inval(mbar1); }
    __syncthreads();
    if (wid == 0) TCGEN05_DEALLOC(tmem_d, 256);
#else
    const int tid = threadIdx.x;
    const int bm = blockIdx.y * 128;
    const int bn = blockIdx.x * 256;
    const int r0 = (tid >> 4) * 8;
    const int c0 = (tid & 15) * 8;
    for (int t = 0; t < ntiles; ++t)
    for (int i = 0; i < 8; ++i) {
        const int row = bm + r0 + i;
        const __nv_bfloat16* ar = A2 + (size_t)row * KSP2;
        for (int j = 0; j < 8; ++j) {
            const int col = bn + t * 128 + c0 + j;
            const __nv_bfloat16* br = B2 + (size_t)col * KSP2;
            float acc = 0.f;
            for (int k = 0; k < 1024; ++k) {
                float ah = __bfloat162float(ar[k]), al = __bfloat162float(ar[1024 + k]);
                float bh = __bfloat162float(br[k]), bl = __bfloat162float(br[1024 + k]);
                acc += ah * bh + ah * bl + al * bh;
            }
            float o = scale * (acc + bias[col]);
            if (RESID) o += resid[(size_t)row * N + col];
            out[(size_t)row * N + col] = o;
        }
    }
#endif
}

// ---------------- chunked scan (round-7 proven form) -------------------------
__global__ void __launch_bounds__(256) scan_phase1_kernel() {
    const int tid = threadIdx.x;
    const int gid = blockIdx.x * 16 + (tid >> 4);
    const int e = tid & 15;
    const int j = gid >> 9;
    const int c = gid & 511;
    const int b = c >> 6, h = c & 63;
    const int t0 = j * CHUNK;

    size_t off = ((size_t)b * LL + t0) * DD + h * HDIM + e;
    size_t offIF = ((size_t)b * LL + t0) * (2 * HH);

    float C[16];
    #pragma unroll
    for (int d = 0; d < 16; ++d) C[d] = 0.f;
    float n = 0.f, m = -1e30f, F = 0.f;

    for (int t = 0; t < CHUNK; ++t) {
        const float ke = g_k[off], ve = g_v[off];
        const float it = g_if[offIF + h];
        const float ft = g_if[offIF + HH + h];
        const float m_new = fmaxf(ft + m, it);
        const float fd = __expf(ft + m - m_new);
        const float id = __expf(it - m_new);
        m = m_new; F += ft;
        const float kid = id * ke;
        n = fd * n + kid;
        #pragma unroll
        for (int d = 0; d < 16; ++d) {
            const float vd = __shfl_sync(0xffffffffu, ve, d, 16);
            C[d] = fd * C[d] + vd * kid;
        }
        off += DD; offIF += 2 * HH;
    }
    float* cs = g_Cloc + (size_t)gid * 256;
    #pragma unroll
    for (int d = 0; d < 16; ++d) cs[d * 16 + e] = C[d];
    g_nloc[(size_t)gid * 16 + e] = n;
    if (e == 0) { g_mloc[gid] = m; g_Floc[gid] = F; }
}

__global__ void __launch_bounds__(256) scan_phase2_kernel() {
    const int tid = threadIdx.x;
    const int c = blockIdx.x * 16 + (tid >> 4);
    const int e = tid & 15;

    float C[16];
    #pragma unroll
    for (int d = 0; d < 16; ++d) C[d] = 0.f;
    float n = 0.f, m = 0.f;

    for (int j = 0; j < NCH; ++j) {
        const int sid = j * NCHAINS + c;
        float* ci = g_Cin + (size_t)sid * 256;
        #pragma unroll
        for (int d = 0; d < 16; ++d) ci[d * 16 + e] = C[d];
        g_nin[(size_t)sid * 16 + e] = n;
        if (e == 0) g_min[sid] = m;
        const float ml = g_mloc[sid];
        const float F  = g_Floc[sid];
        const float mo = fmaxf(m + F, ml);
        const float a  = __expf(m + F - mo);
        const float bb = __expf(ml - mo);
        const float* cl = g_Cloc + (size_t)sid * 256;
        #pragma unroll
        for (int d = 0; d < 16; ++d) C[d] = a * C[d] + bb * cl[d * 16 + e];
        n = a * n + bb * g_nloc[(size_t)sid * 16 + e];
        m = mo;
    }
}

__global__ void __launch_bounds__(256) scan_phase3_kernel() {
    const int tid = threadIdx.x;
    const int gid = blockIdx.x * 16 + (tid >> 4);
    const int e = tid & 15;
    const int j = gid >> 9;
    const int c = gid & 511;
    const int b = c >> 6, h = c & 63;
    const int t0 = j * CHUNK;

    size_t off = ((size_t)b * LL + t0) * DD + h * HDIM + e;
    size_t offIF = ((size_t)b * LL + t0) * (2 * HH);
    size_t h2off = ((size_t)b * LL + t0) * KSP2 + h * HDIM + e;

    const float* ci = g_Cin + (size_t)gid * 256;
    float C[16];
    #pragma unroll
    for (int d = 0; d < 16; ++d) C[d] = ci[d * 16 + e];
    float n = g_nin[(size_t)gid * 16 + e];
    float m = g_min[gid];

    for (int t = 0; t < CHUNK; ++t) {
        const float qe = g_q[off], ke = g_k[off], ve = g_v[off];
        const float it = g_if[offIF + h];
        const float ft = g_if[offIF + HH + h];
        const float m_new = fmaxf(ft + m, it);
        const float fd = __expf(ft + m - m_new);
        const float id = __expf(it - m_new);
        m = m_new;
        const float kid = id * ke;
        n = fd * n + kid;

        float cq = 0.f;
        #pragma unroll
        for (int d = 0; d < 16; ++d) {
            const float vd = __shfl_sync(0xffffffffu, ve, d, 16);
            const float qd = __shfl_sync(0xffffffffu, qe, d, 16);
            C[d] = fd * C[d] + vd * kid;
            cq = fmaf(C[d], qd, cq);
        }

        float nq = n * qe;
        #pragma unroll
        for (int o = 8; o; o >>= 1) nq += __shfl_xor_sync(0xffffffffu, nq, o, 16);
        const float denom = fmaxf(fabsf(nq), 1.0f);

        const float hval = cq / denom;
        __nv_bfloat16 hh, hl;
        split2(hval, hh, hl);
        g_h2[h2off] = hh;
        g_h2[h2off + 1024] = hl;

        off += DD; offIF += 2 * HH; h2off += KSP2;
    }
}

// ---------------- launch ----------------------------------------------------
extern "C" void kernel_launch(void* const* d_in, const int* in_sizes, int n_in,
                              void* d_out, int out_size) {
    (void)in_sizes; (void)n_in; (void)out_size;
    const float* x     = (const float*)d_in[0];
    const float* gamma = (const float*)d_in[1];
    const float* beta  = (const float*)d_in[2];
    const float* qw    = (const float*)d_in[3];
    const float* qb    = (const float*)d_in[4];
    const float* kw    = (const float*)d_in[5];
    const float* kb    = (const float*)d_in[6];
    const float* vw    = (const float*)d_in[7];
    const float* vb    = (const float*)d_in[8];
    const float* ow    = (const float*)d_in[9];
    const float* ob    = (const float*)d_in[10];
    const float* iw    = (const float*)d_in[11];
    const float* ib    = (const float*)d_in[12];
    const float* fw    = (const float*)d_in[13];
    const float* fb    = (const float*)d_in[14];
    float* out = (float*)d_out;

    __nv_bfloat16 *a2, *h2, *qw2, *kw2, *vw2, *ow2, *wif2;
    float *qp, *kp, *vp, *ifp, *wif, *bif;
    cudaGetSymbolAddress((void**)&a2,   g_a2);
    cudaGetSymbolAddress((void**)&h2,   g_h2);
    cudaGetSymbolAddress((void**)&qw2,  g_qw2);
    cudaGetSymbolAddress((void**)&kw2,  g_kw2);
    cudaGetSymbolAddress((void**)&vw2,  g_vw2);
    cudaGetSymbolAddress((void**)&ow2,  g_ow2);
    cudaGetSymbolAddress((void**)&wif2, g_wif2);
    cudaGetSymbolAddress((void**)&qp,   g_q);
    cudaGetSymbolAddress((void**)&kp,   g_k);
    cudaGetSymbolAddress((void**)&vp,   g_v);
    cudaGetSymbolAddress((void**)&ifp,  g_if);
    cudaGetSymbolAddress((void**)&wif,  g_wif);
    cudaGetSymbolAddress((void**)&bif,  g_bif);

    cudaFuncSetAttribute(mma_gemm_qkv_kernel,
                         cudaFuncAttributeMaxDynamicSharedMemorySize, SMEM_SZ);
    cudaFuncSetAttribute(mma_gemm_cg2_kernel<true>,
                         cudaFuncAttributeMaxDynamicSharedMemorySize, SMEM_SZ);
    cudaFuncSetAttribute(mma_gemm_kernel<false>,
                         cudaFuncAttributeMaxDynamicSharedMemorySize, SMEM_SZ);

    dim3 gridQKV(12, MROWS / 256);               // 1536 CTAs (768 pairs)
    dim3 gridCg2(2 * (DD / 512), MROWS / 256);   // (4, 128)
    dim3 gridIF(1, MROWS / 128);                 // (1, 256)

    // launch order: my idx 4 == process idx 5 (one harness launch precedes)
    ln_split_kernel<<<MROWS, 256>>>(x, gamma, beta);                          // 0
    split_kernel<<<(DD * 256 + 255) / 256, 256>>>(qw, qw2, DD);               // 1
    split_kernel<<<(DD * 256 + 255) / 256, 256>>>(kw, kw2, DD);               // 2
    split_kernel<<<(DD * 256 + 255) / 256, 256>>>(vw, vw2, DD);               // 3
    mma_gemm_qkv_kernel<<<gridQKV, 256, SMEM_SZ>>>(a2, qw2, kw2, vw2,
                                                   qb, kb, vb, qp, kp, vp);   // 4 <- ncu
    combine_if_kernel<<<(2 * HH * DD + 255) / 256, 256>>>(iw, ib, fw, fb);    // 5
    split_kernel<<<(2 * HH * 256 + 255) / 256, 256>>>(wif, wif2, 2 * HH);     // 6
    split_kernel<<<(DD * 256 + 255) / 256, 256>>>(ow, ow2, DD);               // 7
    mma_gemm_kernel<false><<<gridIF, 256, SMEM_SZ>>>(a2, wif2, bif, nullptr, ifp, 2 * HH, 1.0f, 1);

    scan_phase1_kernel<<<NSUM / 16, 256>>>();
    scan_phase2_kernel<<<NCHAINS / 16, 256>>>();
    scan_phase3_kernel<<<NSUM / 16, 256>>>();

    mma_gemm_cg2_kernel<true><<<gridCg2, 256, SMEM_SZ>>>(h2, ow2, ob, x, out, DD, 1.0f);
}